// round 3
// baseline (speedup 1.0000x reference)
#include <cuda_runtime.h>
#include <cstdint>

#define N_NODES 50000
#define N_EDGES 600000
#define D_IN 128
#define D_HID 256
#define D_OUT 128

// ---------------- scratch (device globals; referenced directly in kernels) ----
__device__ float g_deg[N_NODES];
__device__ float g_dinv[N_NODES];
__device__ float g_ew[N_EDGES];           // softplus(edge_weights)
__device__ float g_norm[N_EDGES];         // dinv[src]*ew*dinv[dst]
__device__ float g_xw[N_NODES * D_HID];   // h @ W result
__device__ float g_agg[N_NODES * D_HID];  // scatter accumulator
__device__ float g_h[N_NODES * D_HID];    // relu output / next layer input

// ---------------- normalization pipeline ----------------
__global__ void k_deg_init() {
    int i = blockIdx.x * blockDim.x + threadIdx.x;
    if (i < N_NODES) g_deg[i] = 1.0f;  // self-loop weight 1
}

__global__ void k_edge_deg(const float* __restrict__ ew_raw,
                           const int* __restrict__ dst) {
    int i = blockIdx.x * blockDim.x + threadIdx.x;
    if (i < N_EDGES) {
        float w = ew_raw[i];
        // softplus, numerically stable: max(x,0) + log1p(exp(-|x|))
        float sp = fmaxf(w, 0.0f) + log1pf(expf(-fabsf(w)));
        g_ew[i] = sp;
        atomicAdd(&g_deg[dst[i]], sp);
    }
}

__global__ void k_dinv() {
    int i = blockIdx.x * blockDim.x + threadIdx.x;
    if (i < N_NODES) {
        float d = g_deg[i];
        g_dinv[i] = (d > 0.0f) ? rsqrtf(d) : 0.0f;
    }
}

__global__ void k_norm(const int* __restrict__ src,
                       const int* __restrict__ dst) {
    int i = blockIdx.x * blockDim.x + threadIdx.x;
    if (i < N_EDGES) {
        g_norm[i] = g_dinv[src[i]] * g_ew[i] * g_dinv[dst[i]];
    }
}

// ---------------- aggregation ----------------
// g_agg[n][j] = b[j] + dinv[n]^2 * g_xw[n][j]   (bias + self-loop)
__global__ void k_init_agg_g(const float* __restrict__ bias, int dim) {
    int idx = blockIdx.x * blockDim.x + threadIdx.x;
    if (idx < N_NODES * dim) {
        int node = idx / dim;
        int j = idx - node * dim;
        float di = g_dinv[node];
        g_agg[idx] = bias[j] + di * di * g_xw[idx];
    }
}

// same, but writing an external output buffer (layer 3 -> d_out)
__global__ void k_init_agg_out(const float* __restrict__ bias,
                               float* __restrict__ agg, int dim) {
    int idx = blockIdx.x * blockDim.x + threadIdx.x;
    if (idx < N_NODES * dim) {
        int node = idx / dim;
        int j = idx - node * dim;
        float di = g_dinv[node];
        agg[idx] = bias[j] + di * di * g_xw[idx];
    }
}

// warp per edge: gather g_xw[src], scale, atomicAdd into g_agg[dst]
__global__ void k_scatter_g(const int* __restrict__ src,
                            const int* __restrict__ dst, int dim) {
    int warp = (blockIdx.x * blockDim.x + threadIdx.x) >> 5;
    int lane = threadIdx.x & 31;
    if (warp >= N_EDGES) return;
    int s = src[warp];
    int d = dst[warp];
    float w = g_norm[warp];
    const float* hs = g_xw + (long)s * dim;
    float* od = g_agg + (long)d * dim;
    #pragma unroll 4
    for (int j = lane; j < dim; j += 32) {
        atomicAdd(&od[j], w * __ldg(&hs[j]));
    }
}

__global__ void k_scatter_out(const int* __restrict__ src,
                              const int* __restrict__ dst,
                              float* __restrict__ agg, int dim) {
    int warp = (blockIdx.x * blockDim.x + threadIdx.x) >> 5;
    int lane = threadIdx.x & 31;
    if (warp >= N_EDGES) return;
    int s = src[warp];
    int d = dst[warp];
    float w = g_norm[warp];
    const float* hs = g_xw + (long)s * dim;
    float* od = agg + (long)d * dim;
    #pragma unroll 4
    for (int j = lane; j < dim; j += 32) {
        atomicAdd(&od[j], w * __ldg(&hs[j]));
    }
}

__global__ void k_relu(int n) {
    int i = blockIdx.x * blockDim.x + threadIdx.x;
    if (i < n) g_h[i] = fmaxf(g_agg[i], 0.0f);
}

// ---------------- fp32 tiled GEMM: g_xw[M,N] = A[M,K] @ B[K,N] --------------
#define TM 64
#define TN 64
#define TK 32

// A read from external pointer (layer 1: A = x)
__global__ __launch_bounds__(256) void k_gemm_x(const float* __restrict__ A,
                                                const float* __restrict__ B,
                                                int M, int K, int N) {
    __shared__ float As[TK][TM + 1];
    __shared__ float Bs[TK][TN];

    int tx = threadIdx.x & 15;
    int ty = threadIdx.x >> 4;
    int row0 = blockIdx.x * TM;
    int col0 = blockIdx.y * TN;

    float acc[4][4] = {};

    for (int k0 = 0; k0 < K; k0 += TK) {
        #pragma unroll
        for (int i = threadIdx.x; i < TM * TK; i += 256) {
            int m = i >> 5;
            int k = i & (TK - 1);
            int gr = row0 + m;
            float v = 0.0f;
            if (gr < M) v = A[(long)gr * K + k0 + k];
            As[k][m] = v;
        }
        #pragma unroll
        for (int i = threadIdx.x; i < TK * TN; i += 256) {
            int k = i >> 6;
            int n = i & (TN - 1);
            Bs[k][n] = B[(long)(k0 + k) * N + col0 + n];
        }
        __syncthreads();

        #pragma unroll
        for (int kk = 0; kk < TK; kk++) {
            float a[4], b[4];
            #pragma unroll
            for (int i = 0; i < 4; i++) a[i] = As[kk][ty * 4 + i];
            #pragma unroll
            for (int j = 0; j < 4; j++) b[j] = Bs[kk][tx * 4 + j];
            #pragma unroll
            for (int i = 0; i < 4; i++)
                #pragma unroll
                for (int j = 0; j < 4; j++)
                    acc[i][j] += a[i] * b[j];
        }
        __syncthreads();
    }

    #pragma unroll
    for (int i = 0; i < 4; i++) {
        int gr = row0 + ty * 4 + i;
        if (gr < M) {
            float* cp = g_xw + (long)gr * N + col0 + tx * 4;
            #pragma unroll
            for (int j = 0; j < 4; j++) cp[j] = acc[i][j];
        }
    }
}

// A read from g_h (layers 2 & 3)
__global__ __launch_bounds__(256) void k_gemm_h(const float* __restrict__ B,
                                                int M, int K, int N) {
    __shared__ float As[TK][TM + 1];
    __shared__ float Bs[TK][TN];

    int tx = threadIdx.x & 15;
    int ty = threadIdx.x >> 4;
    int row0 = blockIdx.x * TM;
    int col0 = blockIdx.y * TN;

    float acc[4][4] = {};

    for (int k0 = 0; k0 < K; k0 += TK) {
        #pragma unroll
        for (int i = threadIdx.x; i < TM * TK; i += 256) {
            int m = i >> 5;
            int k = i & (TK - 1);
            int gr = row0 + m;
            float v = 0.0f;
            if (gr < M) v = g_h[(long)gr * K + k0 + k];
            As[k][m] = v;
        }
        #pragma unroll
        for (int i = threadIdx.x; i < TK * TN; i += 256) {
            int k = i >> 6;
            int n = i & (TN - 1);
            Bs[k][n] = B[(long)(k0 + k) * N + col0 + n];
        }
        __syncthreads();

        #pragma unroll
        for (int kk = 0; kk < TK; kk++) {
            float a[4], b[4];
            #pragma unroll
            for (int i = 0; i < 4; i++) a[i] = As[kk][ty * 4 + i];
            #pragma unroll
            for (int j = 0; j < 4; j++) b[j] = Bs[kk][tx * 4 + j];
            #pragma unroll
            for (int i = 0; i < 4; i++)
                #pragma unroll
                for (int j = 0; j < 4; j++)
                    acc[i][j] += a[i] * b[j];
        }
        __syncthreads();
    }

    #pragma unroll
    for (int i = 0; i < 4; i++) {
        int gr = row0 + ty * 4 + i;
        if (gr < M) {
            float* cp = g_xw + (long)gr * N + col0 + tx * 4;
            #pragma unroll
            for (int j = 0; j < 4; j++) cp[j] = acc[i][j];
        }
    }
}

// ---------------- launch ----------------
extern "C" void kernel_launch(void* const* d_in, const int* in_sizes, int n_in,
                              void* d_out, int out_size) {
    const float* x      = (const float*)d_in[0];
    const int*   ei     = (const int*)d_in[1];     // int32! (harness downcasts int64)
    const float* ew_raw = (const float*)d_in[2];
    const float* W1     = (const float*)d_in[3];
    const float* b1     = (const float*)d_in[4];
    const float* W2     = (const float*)d_in[5];
    const float* b2     = (const float*)d_in[6];
    const float* W3     = (const float*)d_in[7];
    const float* b3     = (const float*)d_in[8];
    float* out          = (float*)d_out;

    const int* src = ei;
    const int* dst = ei + N_EDGES;

    const int T = 256;
    int nb_nodes = (N_NODES + T - 1) / T;
    int nb_edges = (N_EDGES + T - 1) / T;

    k_deg_init<<<nb_nodes, T>>>();
    k_edge_deg<<<nb_edges, T>>>(ew_raw, dst);
    k_dinv<<<nb_nodes, T>>>();
    k_norm<<<nb_edges, T>>>(src, dst);

    int gm = (N_NODES + TM - 1) / TM;                 // 782
    int scatter_blocks = (N_EDGES * 32 + T - 1) / T;  // warp per edge

    // --- layer 1: x[50000,128] @ W1[128,256] ---
    {
        dim3 grid(gm, D_HID / TN);
        k_gemm_x<<<grid, 256>>>(x, W1, N_NODES, D_IN, D_HID);
        k_init_agg_g<<<(N_NODES * D_HID + T - 1) / T, T>>>(b1, D_HID);
        k_scatter_g<<<scatter_blocks, T>>>(src, dst, D_HID);
        k_relu<<<(N_NODES * D_HID + T - 1) / T, T>>>(N_NODES * D_HID);
    }

    // --- layer 2: h[50000,256] @ W2[256,256] ---
    {
        dim3 grid(gm, D_HID / TN);
        k_gemm_h<<<grid, 256>>>(W2, N_NODES, D_HID, D_HID);
        k_init_agg_g<<<(N_NODES * D_HID + T - 1) / T, T>>>(b2, D_HID);
        k_scatter_g<<<scatter_blocks, T>>>(src, dst, D_HID);
        k_relu<<<(N_NODES * D_HID + T - 1) / T, T>>>(N_NODES * D_HID);
    }

    // --- layer 3: h[50000,256] @ W3[256,128] -> d_out ---
    {
        dim3 grid(gm, D_OUT / TN);
        k_gemm_h<<<grid, 256>>>(W3, N_NODES, D_HID, D_OUT);
        k_init_agg_out<<<(N_NODES * D_OUT + T - 1) / T, T>>>(b3, out, D_OUT);
        k_scatter_out<<<scatter_blocks, T>>>(src, dst, out, D_OUT);
    }
}

// round 4
// speedup vs baseline: 1.5884x; 1.5884x over previous
#include <cuda_runtime.h>
#include <cstdint>

#define N_NODES 50000
#define N_EDGES 600000
#define D_IN 128
#define D_HID 256
#define D_OUT 128

// ---------------- scratch (device globals; referenced directly) -------------
__device__ float g_deg[N_NODES];
__device__ float g_dinv[N_NODES];
__device__ float g_ew[N_EDGES];            // softplus(edge_weights)
__device__ int   g_cnt[N_NODES];           // in-degree (edges only)
__device__ int   g_rowptr[N_NODES + 1];    // CSR row pointers (by dst)
__device__ int   g_fill[N_NODES];          // placement cursors
__device__ int   g_csr_src[N_EDGES];       // src node per CSR slot
__device__ float g_csr_w[N_EDGES];         // edge norm per CSR slot
__device__ float g_agg[N_NODES * D_HID];   // aggregation output
__device__ float g_h[N_NODES * D_HID];     // layer activations
__device__ float g_xw[N_NODES * D_HID];    // layer-3 transform output

// ---------------- prep: degrees, softplus, CSR ------------------------------
__global__ void k_init() {
    int i = blockIdx.x * blockDim.x + threadIdx.x;
    if (i < N_NODES) { g_deg[i] = 1.0f; g_cnt[i] = 0; }  // self-loop weight 1
}

__global__ void k_edge_prep(const float* __restrict__ ew_raw,
                            const int* __restrict__ dst) {
    int i = blockIdx.x * blockDim.x + threadIdx.x;
    if (i < N_EDGES) {
        float w = ew_raw[i];
        float sp = fmaxf(w, 0.0f) + log1pf(expf(-fabsf(w)));  // stable softplus
        g_ew[i] = sp;
        int d = dst[i];
        atomicAdd(&g_deg[d], sp);
        atomicAdd(&g_cnt[d], 1);
    }
}

__global__ void k_dinv() {
    int i = blockIdx.x * blockDim.x + threadIdx.x;
    if (i < N_NODES) g_dinv[i] = rsqrtf(g_deg[i]);  // deg >= 1 always
}

// single-block chunked exclusive scan of g_cnt -> g_rowptr, g_fill
__global__ void k_scan() {
    __shared__ int s[1024];
    __shared__ int carry_s;
    int tid = threadIdx.x;
    if (tid == 0) carry_s = 0;
    __syncthreads();
    for (int base = 0; base < N_NODES; base += 1024) {
        int i = base + tid;
        int v = (i < N_NODES) ? g_cnt[i] : 0;
        s[tid] = v;
        __syncthreads();
        #pragma unroll
        for (int off = 1; off < 1024; off <<= 1) {
            int t = (tid >= off) ? s[tid - off] : 0;
            __syncthreads();
            s[tid] += t;
            __syncthreads();
        }
        int excl = s[tid] - v + carry_s;
        if (i < N_NODES) { g_rowptr[i] = excl; g_fill[i] = excl; }
        __syncthreads();
        if (tid == 0) carry_s += s[1023];
        __syncthreads();
    }
    if (tid == 0) g_rowptr[N_NODES] = carry_s;
}

__global__ void k_place(const int* __restrict__ src,
                        const int* __restrict__ dst) {
    int i = blockIdx.x * blockDim.x + threadIdx.x;
    if (i < N_EDGES) {
        int s = src[i], d = dst[i];
        float w = g_dinv[s] * g_ew[i] * g_dinv[d];
        int pos = atomicAdd(&g_fill[d], 1);
        g_csr_src[pos] = s;
        g_csr_w[pos] = w;
    }
}

// ---------------- aggregation: warp per node, CSR gather ---------------------
// dst[n] = dinv[n]^2 * srcmat[n] + sum_{e in-edges(n)} w_e * srcmat[src_e] (+bias)
template <int DIM, bool ADD_BIAS>
__device__ __forceinline__ void agg_body(const float* __restrict__ srcmat,
                                         float* __restrict__ dstmat,
                                         const float* __restrict__ bias) {
    int warp = (blockIdx.x * blockDim.x + threadIdx.x) >> 5;
    int lane = threadIdx.x & 31;
    if (warp >= N_NODES) return;
    constexpr int V = DIM / 128;  // float4s per lane (1 or 2)

    int start = g_rowptr[warp];
    int end   = g_rowptr[warp + 1];
    float di = g_dinv[warp];
    float w0 = di * di;

    float4 acc[V];
    const float4* selfrow = (const float4*)(srcmat + (size_t)warp * DIM);
    #pragma unroll
    for (int v = 0; v < V; v++) {
        float4 t = __ldg(&selfrow[lane + 32 * v]);
        acc[v] = make_float4(w0 * t.x, w0 * t.y, w0 * t.z, w0 * t.w);
    }

    int e = start;
    for (; e + 1 < end; e += 2) {
        int   s0 = g_csr_src[e],     s1 = g_csr_src[e + 1];
        float w1 = g_csr_w[e],       w2 = g_csr_w[e + 1];
        const float4* r0 = (const float4*)(srcmat + (size_t)s0 * DIM);
        const float4* r1 = (const float4*)(srcmat + (size_t)s1 * DIM);
        #pragma unroll
        for (int v = 0; v < V; v++) {
            float4 x0 = __ldg(&r0[lane + 32 * v]);
            float4 x1 = __ldg(&r1[lane + 32 * v]);
            acc[v].x += w1 * x0.x + w2 * x1.x;
            acc[v].y += w1 * x0.y + w2 * x1.y;
            acc[v].z += w1 * x0.z + w2 * x1.z;
            acc[v].w += w1 * x0.w + w2 * x1.w;
        }
    }
    if (e < end) {
        int s0 = g_csr_src[e];
        float w1 = g_csr_w[e];
        const float4* r0 = (const float4*)(srcmat + (size_t)s0 * DIM);
        #pragma unroll
        for (int v = 0; v < V; v++) {
            float4 x0 = __ldg(&r0[lane + 32 * v]);
            acc[v].x += w1 * x0.x; acc[v].y += w1 * x0.y;
            acc[v].z += w1 * x0.z; acc[v].w += w1 * x0.w;
        }
    }

    float4* drow = (float4*)(dstmat + (size_t)warp * DIM);
    #pragma unroll
    for (int v = 0; v < V; v++) {
        if (ADD_BIAS) {
            float4 b = __ldg(&((const float4*)bias)[lane + 32 * v]);
            acc[v].x += b.x; acc[v].y += b.y; acc[v].z += b.z; acc[v].w += b.w;
        }
        drow[lane + 32 * v] = acc[v];
    }
}

__global__ void k_agg_x(const float* __restrict__ x) {
    agg_body<128, false>(x, g_agg, nullptr);
}
__global__ void k_agg_h() {
    agg_body<256, false>(g_h, g_agg, nullptr);
}
__global__ void k_agg_out(float* __restrict__ out, const float* __restrict__ b3) {
    agg_body<128, true>(g_xw, out, b3);
}

// ---------------- fp32 GEMM: C[M,N] = A[M,K] @ B[K,N], 128x128x8 ------------
// MODE 0: plain store.  MODE 1: C = relu(A@B + bias)
template <int MODE>
__device__ __forceinline__ void gemm_body(const float* __restrict__ A,
                                          const float* __restrict__ B,
                                          const float* __restrict__ bias,
                                          float* __restrict__ C,
                                          int M, int K, int N) {
    __shared__ float As[2][8][132];   // transposed A tile, padded
    __shared__ float Bs[2][8][128];

    int tid = threadIdx.x;
    int tx = tid & 15;       // 0..15 -> 8-col group
    int ty = tid >> 4;       // 0..15 -> 8-row group
    int row0 = blockIdx.x * 128;
    int col0 = blockIdx.y * 128;

    int arow = tid >> 1;            // 0..127
    int acol = (tid & 1) * 4;       // 0 or 4
    int brow = tid >> 5;            // 0..7
    int bcol = (tid & 31) * 4;      // 0..124

    float acc[8][8] = {};

    // load tile 0
    {
        int gr = row0 + arow;
        float4 av = (gr < M) ? *(const float4*)(A + (size_t)gr * K + acol)
                             : make_float4(0.f, 0.f, 0.f, 0.f);
        As[0][acol + 0][arow] = av.x;
        As[0][acol + 1][arow] = av.y;
        As[0][acol + 2][arow] = av.z;
        As[0][acol + 3][arow] = av.w;
        *(float4*)&Bs[0][brow][bcol] = *(const float4*)(B + (size_t)brow * N + col0 + bcol);
    }
    __syncthreads();

    int ktiles = K >> 3;
    int p = 0;
    for (int t = 0; t < ktiles; t++) {
        float4 av, bv;
        bool more = (t + 1 < ktiles);
        if (more) {
            int k0 = (t + 1) << 3;
            int gr = row0 + arow;
            av = (gr < M) ? *(const float4*)(A + (size_t)gr * K + k0 + acol)
                          : make_float4(0.f, 0.f, 0.f, 0.f);
            bv = *(const float4*)(B + (size_t)(k0 + brow) * N + col0 + bcol);
        }

        #pragma unroll
        for (int k = 0; k < 8; k++) {
            float a[8], b[8];
            *(float4*)&a[0] = *(const float4*)&As[p][k][ty * 8];
            *(float4*)&a[4] = *(const float4*)&As[p][k][ty * 8 + 4];
            *(float4*)&b[0] = *(const float4*)&Bs[p][k][tx * 8];
            *(float4*)&b[4] = *(const float4*)&Bs[p][k][tx * 8 + 4];
            #pragma unroll
            for (int i = 0; i < 8; i++)
                #pragma unroll
                for (int j = 0; j < 8; j++)
                    acc[i][j] += a[i] * b[j];
        }

        if (more) {
            int q = p ^ 1;
            As[q][acol + 0][arow] = av.x;
            As[q][acol + 1][arow] = av.y;
            As[q][acol + 2][arow] = av.z;
            As[q][acol + 3][arow] = av.w;
            *(float4*)&Bs[q][brow][bcol] = bv;
        }
        __syncthreads();
        p ^= 1;
    }

    float bb[8];
    if (MODE == 1) {
        #pragma unroll
        for (int j = 0; j < 8; j++) bb[j] = __ldg(&bias[col0 + tx * 8 + j]);
    }

    #pragma unroll
    for (int i = 0; i < 8; i++) {
        int gr = row0 + ty * 8 + i;
        if (gr < M) {
            float* cp = C + (size_t)gr * N + col0 + tx * 8;
            #pragma unroll
            for (int j0 = 0; j0 < 8; j0 += 4) {
                float4 v;
                v.x = acc[i][j0 + 0]; v.y = acc[i][j0 + 1];
                v.z = acc[i][j0 + 2]; v.w = acc[i][j0 + 3];
                if (MODE == 1) {
                    v.x = fmaxf(v.x + bb[j0 + 0], 0.f);
                    v.y = fmaxf(v.y + bb[j0 + 1], 0.f);
                    v.z = fmaxf(v.z + bb[j0 + 2], 0.f);
                    v.w = fmaxf(v.w + bb[j0 + 3], 0.f);
                }
                *(float4*)(cp + j0) = v;
            }
        }
    }
}

__global__ __launch_bounds__(256) void k_gemm1(const float* __restrict__ W1,
                                               const float* __restrict__ b1) {
    gemm_body<1>(g_agg, W1, b1, g_h, N_NODES, D_IN, D_HID);
}
__global__ __launch_bounds__(256) void k_gemm2(const float* __restrict__ W2,
                                               const float* __restrict__ b2) {
    gemm_body<1>(g_agg, W2, b2, g_h, N_NODES, D_HID, D_HID);
}
__global__ __launch_bounds__(256) void k_gemm3(const float* __restrict__ W3) {
    gemm_body<0>(g_h, W3, nullptr, g_xw, N_NODES, D_HID, D_OUT);
}

// ---------------- launch -----------------------------------------------------
extern "C" void kernel_launch(void* const* d_in, const int* in_sizes, int n_in,
                              void* d_out, int out_size) {
    const float* x      = (const float*)d_in[0];
    const int*   ei     = (const int*)d_in[1];     // int32 (harness downcasts int64)
    const float* ew_raw = (const float*)d_in[2];
    const float* W1     = (const float*)d_in[3];
    const float* b1     = (const float*)d_in[4];
    const float* W2     = (const float*)d_in[5];
    const float* b2     = (const float*)d_in[6];
    const float* W3     = (const float*)d_in[7];
    const float* b3     = (const float*)d_in[8];
    float* out          = (float*)d_out;

    const int* src = ei;
    const int* dst = ei + N_EDGES;

    const int T = 256;
    int nb_nodes = (N_NODES + T - 1) / T;
    int nb_edges = (N_EDGES + T - 1) / T;
    int agg_blocks = (N_NODES * 32 + T - 1) / T;   // warp per node
    int gm = (N_NODES + 127) / 128;                // 391

    // CSR + normalization prep
    k_init<<<nb_nodes, T>>>();
    k_edge_prep<<<nb_edges, T>>>(ew_raw, dst);
    k_dinv<<<nb_nodes, T>>>();
    k_scan<<<1, 1024>>>();
    k_place<<<nb_edges, T>>>(src, dst);

    // layer 1: agg(x) [128] -> @W1 + b1, relu
    k_agg_x<<<agg_blocks, T>>>(x);
    k_gemm1<<<dim3(gm, 2), 256>>>(W1, b1);

    // layer 2: agg(h) [256] -> @W2 + b2, relu
    k_agg_h<<<agg_blocks, T>>>();
    k_gemm2<<<dim3(gm, 2), 256>>>(W2, b2);

    // layer 3: h @ W3 [->128], then agg + b3 -> out
    k_gemm3<<<dim3(gm, 1), 256>>>(W3);
    k_agg_out<<<agg_blocks, T>>>(out, b3);
}

// round 5
// speedup vs baseline: 3.2917x; 2.0724x over previous
#include <cuda_runtime.h>
#include <cstdint>

#define N_NODES 50000
#define N_EDGES 600000
#define D_IN 128
#define D_HID 256
#define D_OUT 128
#define SCAN_B 1024
#define NCHUNK ((N_NODES + SCAN_B - 1) / SCAN_B)   // 49

// ---------------- scratch (device globals) ----------------------------------
__device__ float g_deg[N_NODES];
__device__ float g_dinv[N_NODES];
__device__ float g_ew[N_EDGES];
__device__ int   g_cnt[N_NODES];
__device__ int   g_rowptr[N_NODES + 1];
__device__ int   g_fill[N_NODES];
__device__ int   g_part[NCHUNK];
__device__ int   g_partscan[NCHUNK];
__device__ int   g_csr_src[N_EDGES];
__device__ float g_csr_w[N_EDGES];
__device__ float g_agg[N_NODES * D_HID];
__device__ float g_h[N_NODES * D_HID];
__device__ float g_xw[N_NODES * D_HID];

// ---------------- prep -------------------------------------------------------
__global__ void k_init() {
    int i = blockIdx.x * blockDim.x + threadIdx.x;
    if (i < N_NODES) { g_deg[i] = 1.0f; g_cnt[i] = 0; }
}

__global__ void k_edge_prep(const float* __restrict__ ew_raw,
                            const int* __restrict__ dst) {
    int i = blockIdx.x * blockDim.x + threadIdx.x;
    if (i < N_EDGES) {
        float w = ew_raw[i];
        float sp = fmaxf(w, 0.0f) + log1pf(expf(-fabsf(w)));
        g_ew[i] = sp;
        int d = dst[i];
        atomicAdd(&g_deg[d], sp);
        atomicAdd(&g_cnt[d], 1);
    }
}

__global__ void k_dinv() {
    int i = blockIdx.x * blockDim.x + threadIdx.x;
    if (i < N_NODES) g_dinv[i] = rsqrtf(g_deg[i]);
}

// ---- parallel scan: chunk scans -> partial scan -> apply offsets ------------
__global__ void k_scan1() {
    __shared__ int s[SCAN_B];
    int b = blockIdx.x, tid = threadIdx.x;
    int i = b * SCAN_B + tid;
    int v = (i < N_NODES) ? g_cnt[i] : 0;
    s[tid] = v;
    __syncthreads();
    #pragma unroll
    for (int off = 1; off < SCAN_B; off <<= 1) {
        int t = (tid >= off) ? s[tid - off] : 0;
        __syncthreads();
        s[tid] += t;
        __syncthreads();
    }
    if (i < N_NODES) g_rowptr[i] = s[tid] - v;   // exclusive within chunk
    if (tid == SCAN_B - 1) g_part[b] = s[tid];
}

__global__ void k_scan2() {   // 1 block, 64 threads
    __shared__ int s[64];
    int tid = threadIdx.x;
    int v = (tid < NCHUNK) ? g_part[tid] : 0;
    s[tid] = v;
    __syncthreads();
    #pragma unroll
    for (int off = 1; off < 64; off <<= 1) {
        int t = (tid >= off) ? s[tid - off] : 0;
        __syncthreads();
        s[tid] += t;
        __syncthreads();
    }
    if (tid < NCHUNK) g_partscan[tid] = s[tid] - v;
    if (tid == NCHUNK - 1) g_rowptr[N_NODES] = s[tid];
}

__global__ void k_scan3() {
    int i = blockIdx.x * blockDim.x + threadIdx.x;
    if (i < N_NODES) {
        int v = g_rowptr[i] + g_partscan[i / SCAN_B];
        g_rowptr[i] = v;
        g_fill[i] = v;
    }
}

__global__ void k_place(const int* __restrict__ src,
                        const int* __restrict__ dst) {
    int i = blockIdx.x * blockDim.x + threadIdx.x;
    if (i < N_EDGES) {
        int s = src[i], d = dst[i];
        float w = g_dinv[s] * g_ew[i] * g_dinv[d];
        int pos = atomicAdd(&g_fill[d], 1);
        g_csr_src[pos] = s;
        g_csr_w[pos] = w;
    }
}

// ---------------- aggregation: warp per node, CSR gather ---------------------
template <int DIM, bool ADD_BIAS>
__device__ __forceinline__ void agg_body(const float* __restrict__ srcmat,
                                         float* __restrict__ dstmat,
                                         const float* __restrict__ bias) {
    int warp = (blockIdx.x * blockDim.x + threadIdx.x) >> 5;
    int lane = threadIdx.x & 31;
    if (warp >= N_NODES) return;
    constexpr int V = DIM / 128;

    int start = g_rowptr[warp];
    int end   = g_rowptr[warp + 1];
    float di = g_dinv[warp];
    float w0 = di * di;

    float4 acc[V];
    const float4* selfrow = (const float4*)(srcmat + (size_t)warp * DIM);
    #pragma unroll
    for (int v = 0; v < V; v++) {
        float4 t = __ldg(&selfrow[lane + 32 * v]);
        acc[v] = make_float4(w0 * t.x, w0 * t.y, w0 * t.z, w0 * t.w);
    }

    int e = start;
    for (; e + 1 < end; e += 2) {
        int   s0 = g_csr_src[e],   s1 = g_csr_src[e + 1];
        float w1 = g_csr_w[e],     w2 = g_csr_w[e + 1];
        const float4* r0 = (const float4*)(srcmat + (size_t)s0 * DIM);
        const float4* r1 = (const float4*)(srcmat + (size_t)s1 * DIM);
        #pragma unroll
        for (int v = 0; v < V; v++) {
            float4 x0 = __ldg(&r0[lane + 32 * v]);
            float4 x1 = __ldg(&r1[lane + 32 * v]);
            acc[v].x += w1 * x0.x + w2 * x1.x;
            acc[v].y += w1 * x0.y + w2 * x1.y;
            acc[v].z += w1 * x0.z + w2 * x1.z;
            acc[v].w += w1 * x0.w + w2 * x1.w;
        }
    }
    if (e < end) {
        int s0 = g_csr_src[e];
        float w1 = g_csr_w[e];
        const float4* r0 = (const float4*)(srcmat + (size_t)s0 * DIM);
        #pragma unroll
        for (int v = 0; v < V; v++) {
            float4 x0 = __ldg(&r0[lane + 32 * v]);
            acc[v].x += w1 * x0.x; acc[v].y += w1 * x0.y;
            acc[v].z += w1 * x0.z; acc[v].w += w1 * x0.w;
        }
    }

    float4* drow = (float4*)(dstmat + (size_t)warp * DIM);
    #pragma unroll
    for (int v = 0; v < V; v++) {
        if (ADD_BIAS) {
            float4 b = __ldg(&((const float4*)bias)[lane + 32 * v]);
            acc[v].x += b.x; acc[v].y += b.y; acc[v].z += b.z; acc[v].w += b.w;
        }
        drow[lane + 32 * v] = acc[v];
    }
}

__global__ void k_agg_x(const float* __restrict__ x) {
    agg_body<128, false>(x, g_agg, nullptr);
}
__global__ void k_agg_h() {
    agg_body<256, false>(g_h, g_agg, nullptr);
}
__global__ void k_agg_out(float* __restrict__ out, const float* __restrict__ b3) {
    agg_body<128, true>(g_xw, out, b3);
}

// ---------------- tf32 tensor-core GEMM --------------------------------------
// C[M,N] = A[M,K] @ B[K,N]; MODE 1: C = relu(C + bias)
__device__ __forceinline__ uint32_t f2tf(float x) {
    uint32_t r;
    asm("cvt.rna.tf32.f32 %0, %1;" : "=r"(r) : "f"(x));
    return r;
}

__device__ __forceinline__ void mma_tf32(float* c, const uint32_t* a, const uint32_t* b) {
    asm volatile(
        "mma.sync.aligned.m16n8k8.row.col.f32.tf32.tf32.f32 "
        "{%0,%1,%2,%3}, {%4,%5,%6,%7}, {%8,%9}, {%0,%1,%2,%3};\n"
        : "+f"(c[0]), "+f"(c[1]), "+f"(c[2]), "+f"(c[3])
        : "r"(a[0]), "r"(a[1]), "r"(a[2]), "r"(a[3]), "r"(b[0]), "r"(b[1]));
}

template <int MODE>
__device__ __forceinline__ void gemm_tc(const float* __restrict__ A,
                                        const float* __restrict__ B,
                                        const float* __restrict__ bias,
                                        float* __restrict__ C,
                                        int M, int K, int N) {
    __shared__ uint32_t As[2][128][20];   // [m][k], stride 20 -> conflict-free frags
    __shared__ uint32_t Bs[2][16][136];   // [k][n], stride 136 -> conflict-free frags

    int tid  = threadIdx.x;
    int lane = tid & 31;
    int warp = tid >> 5;
    int gid  = lane >> 2;   // 0..7
    int tig  = lane & 3;    // 0..3
    int wm   = warp >> 2;   // 0..1 -> m offset *64
    int wn   = warp & 3;    // 0..3 -> n offset *32
    int row0 = blockIdx.x * 128;
    int col0 = blockIdx.y * 128;

    int arow = tid >> 2;          // 0..63 (plus +64 for second half)
    int acol = (tid & 3) * 4;     // 0,4,8,12
    int brow = tid >> 5;          // 0..7 (plus +8)
    int bcol = (tid & 31) * 4;

    float acc[4][4][4];
    #pragma unroll
    for (int mt = 0; mt < 4; mt++)
        #pragma unroll
        for (int nt = 0; nt < 4; nt++)
            #pragma unroll
            for (int r = 0; r < 4; r++) acc[mt][nt][r] = 0.f;

    const float4 f4z = make_float4(0.f, 0.f, 0.f, 0.f);

    // load k-tile 0
    {
        int r0 = row0 + arow, r1 = row0 + arow + 64;
        float4 a0 = (r0 < M) ? *(const float4*)(A + (size_t)r0 * K + acol) : f4z;
        float4 a1 = (r1 < M) ? *(const float4*)(A + (size_t)r1 * K + acol) : f4z;
        As[0][arow][acol+0]=f2tf(a0.x); As[0][arow][acol+1]=f2tf(a0.y);
        As[0][arow][acol+2]=f2tf(a0.z); As[0][arow][acol+3]=f2tf(a0.w);
        As[0][arow+64][acol+0]=f2tf(a1.x); As[0][arow+64][acol+1]=f2tf(a1.y);
        As[0][arow+64][acol+2]=f2tf(a1.z); As[0][arow+64][acol+3]=f2tf(a1.w);
        float4 b0 = *(const float4*)(B + (size_t)brow * N + col0 + bcol);
        float4 b1 = *(const float4*)(B + (size_t)(brow + 8) * N + col0 + bcol);
        Bs[0][brow][bcol+0]=f2tf(b0.x); Bs[0][brow][bcol+1]=f2tf(b0.y);
        Bs[0][brow][bcol+2]=f2tf(b0.z); Bs[0][brow][bcol+3]=f2tf(b0.w);
        Bs[0][brow+8][bcol+0]=f2tf(b1.x); Bs[0][brow+8][bcol+1]=f2tf(b1.y);
        Bs[0][brow+8][bcol+2]=f2tf(b1.z); Bs[0][brow+8][bcol+3]=f2tf(b1.w);
    }
    __syncthreads();

    int ktiles = K >> 4;
    int p = 0;
    for (int t = 0; t < ktiles; t++) {
        float4 av0, av1, bv0, bv1;
        bool more = (t + 1 < ktiles);
        if (more) {
            int kb = (t + 1) << 4;
            int r0 = row0 + arow, r1 = row0 + arow + 64;
            av0 = (r0 < M) ? *(const float4*)(A + (size_t)r0 * K + kb + acol) : f4z;
            av1 = (r1 < M) ? *(const float4*)(A + (size_t)r1 * K + kb + acol) : f4z;
            bv0 = *(const float4*)(B + (size_t)(kb + brow) * N + col0 + bcol);
            bv1 = *(const float4*)(B + (size_t)(kb + brow + 8) * N + col0 + bcol);
        }

        #pragma unroll
        for (int kk = 0; kk < 2; kk++) {
            uint32_t af[4][4], bf[4][2];
            #pragma unroll
            for (int mt = 0; mt < 4; mt++) {
                int r = wm * 64 + mt * 16 + gid;
                af[mt][0] = As[p][r][kk*8 + tig];
                af[mt][1] = As[p][r + 8][kk*8 + tig];
                af[mt][2] = As[p][r][kk*8 + tig + 4];
                af[mt][3] = As[p][r + 8][kk*8 + tig + 4];
            }
            #pragma unroll
            for (int nt = 0; nt < 4; nt++) {
                int c = wn * 32 + nt * 8 + gid;
                bf[nt][0] = Bs[p][kk*8 + tig][c];
                bf[nt][1] = Bs[p][kk*8 + tig + 4][c];
            }
            #pragma unroll
            for (int mt = 0; mt < 4; mt++)
                #pragma unroll
                for (int nt = 0; nt < 4; nt++)
                    mma_tf32(acc[mt][nt], af[mt], bf[nt]);
        }

        if (more) {
            int q = p ^ 1;
            As[q][arow][acol+0]=f2tf(av0.x); As[q][arow][acol+1]=f2tf(av0.y);
            As[q][arow][acol+2]=f2tf(av0.z); As[q][arow][acol+3]=f2tf(av0.w);
            As[q][arow+64][acol+0]=f2tf(av1.x); As[q][arow+64][acol+1]=f2tf(av1.y);
            As[q][arow+64][acol+2]=f2tf(av1.z); As[q][arow+64][acol+3]=f2tf(av1.w);
            Bs[q][brow][bcol+0]=f2tf(bv0.x); Bs[q][brow][bcol+1]=f2tf(bv0.y);
            Bs[q][brow][bcol+2]=f2tf(bv0.z); Bs[q][brow][bcol+3]=f2tf(bv0.w);
            Bs[q][brow+8][bcol+0]=f2tf(bv1.x); Bs[q][brow+8][bcol+1]=f2tf(bv1.y);
            Bs[q][brow+8][bcol+2]=f2tf(bv1.z); Bs[q][brow+8][bcol+3]=f2tf(bv1.w);
        }
        __syncthreads();
        p ^= 1;
    }

    // epilogue
    #pragma unroll
    for (int mt = 0; mt < 4; mt++) {
        #pragma unroll
        for (int half = 0; half < 2; half++) {
            int r = row0 + wm * 64 + mt * 16 + gid + half * 8;
            if (r < M) {
                #pragma unroll
                for (int nt = 0; nt < 4; nt++) {
                    int c = col0 + wn * 32 + nt * 8 + tig * 2;
                    float v0 = acc[mt][nt][half * 2 + 0];
                    float v1 = acc[mt][nt][half * 2 + 1];
                    if (MODE == 1) {
                        v0 = fmaxf(v0 + __ldg(&bias[c]), 0.f);
                        v1 = fmaxf(v1 + __ldg(&bias[c + 1]), 0.f);
                    }
                    *(float2*)(C + (size_t)r * N + c) = make_float2(v0, v1);
                }
            }
        }
    }
}

__global__ __launch_bounds__(256) void k_gemm1(const float* __restrict__ W1,
                                               const float* __restrict__ b1) {
    gemm_tc<1>(g_agg, W1, b1, g_h, N_NODES, D_IN, D_HID);
}
__global__ __launch_bounds__(256) void k_gemm2(const float* __restrict__ W2,
                                               const float* __restrict__ b2) {
    gemm_tc<1>(g_agg, W2, b2, g_h, N_NODES, D_HID, D_HID);
}
__global__ __launch_bounds__(256) void k_gemm3(const float* __restrict__ W3) {
    gemm_tc<0>(g_h, W3, nullptr, g_xw, N_NODES, D_HID, D_OUT);
}

// ---------------- launch -----------------------------------------------------
extern "C" void kernel_launch(void* const* d_in, const int* in_sizes, int n_in,
                              void* d_out, int out_size) {
    const float* x      = (const float*)d_in[0];
    const int*   ei     = (const int*)d_in[1];   // int32 (harness downcasts int64)
    const float* ew_raw = (const float*)d_in[2];
    const float* W1     = (const float*)d_in[3];
    const float* b1     = (const float*)d_in[4];
    const float* W2     = (const float*)d_in[5];
    const float* b2     = (const float*)d_in[6];
    const float* W3     = (const float*)d_in[7];
    const float* b3     = (const float*)d_in[8];
    float* out          = (float*)d_out;

    const int* src = ei;
    const int* dst = ei + N_EDGES;

    const int T = 256;
    int nb_nodes = (N_NODES + T - 1) / T;
    int nb_edges = (N_EDGES + T - 1) / T;
    int agg_blocks = (N_NODES * 32 + T - 1) / T;
    int gm = (N_NODES + 127) / 128;   // 391

    // prep: degrees + softplus + CSR
    k_init<<<nb_nodes, T>>>();
    k_edge_prep<<<nb_edges, T>>>(ew_raw, dst);
    k_dinv<<<nb_nodes, T>>>();
    k_scan1<<<NCHUNK, SCAN_B>>>();
    k_scan2<<<1, 64>>>();
    k_scan3<<<nb_nodes, T>>>();
    k_place<<<nb_edges, T>>>(src, dst);

    // layer 1: agg(x)[128] -> relu(@W1 + b1)
    k_agg_x<<<agg_blocks, T>>>(x);
    k_gemm1<<<dim3(gm, 2), 256>>>(W1, b1);

    // layer 2: agg(h)[256] -> relu(@W2 + b2)
    k_agg_h<<<agg_blocks, T>>>();
    k_gemm2<<<dim3(gm, 2), 256>>>(W2, b2);

    // layer 3: h @ W3 [->128], then agg + b3 -> out
    k_gemm3<<<dim3(gm, 1), 256>>>(W3);
    k_agg_out<<<agg_blocks, T>>>(out, b3);
}

// round 6
// speedup vs baseline: 4.2887x; 1.3029x over previous
#include <cuda_runtime.h>
#include <cuda_fp16.h>
#include <cstdint>

#define N_NODES 50000
#define N_EDGES 600000
#define D_IN 128
#define D_HID 256
#define D_OUT 128
#define SCAN_B 1024
#define NCHUNK ((N_NODES + SCAN_B - 1) / SCAN_B)   // 49

// ---------------- scratch (device globals) ----------------------------------
__device__ float g_deg[N_NODES];
__device__ float g_dinv[N_NODES];
__device__ float g_ew[N_EDGES];
__device__ int   g_cnt[N_NODES];
__device__ int   g_rowptr[N_NODES + 1];
__device__ int   g_fill[N_NODES];
__device__ int   g_part[NCHUNK];
__device__ int   g_partscan[NCHUNK];
__device__ int   g_csr_src[N_EDGES];
__device__ float g_csr_w[N_EDGES];
__device__ __align__(256) __half g_xh[N_NODES * D_IN];    // x converted to half
__device__ __align__(256) __half g_agg[N_NODES * D_HID];  // aggregation out (GEMM A)
__device__ __align__(256) __half g_h[N_NODES * D_HID];    // GEMM out (agg src)
__device__ __align__(256) __half g_xw[N_NODES * D_OUT];   // layer-3 transform out

// ---------------- prep -------------------------------------------------------
__global__ void k_init() {
    int i = blockIdx.x * blockDim.x + threadIdx.x;
    if (i < N_NODES) { g_deg[i] = 1.0f; g_cnt[i] = 0; }
}

__global__ void k_edge_prep(const float* __restrict__ ew_raw,
                            const int* __restrict__ dst) {
    int i = blockIdx.x * blockDim.x + threadIdx.x;
    if (i < N_EDGES) {
        float w = ew_raw[i];
        float sp = fmaxf(w, 0.0f) + log1pf(expf(-fabsf(w)));
        g_ew[i] = sp;
        int d = dst[i];
        atomicAdd(&g_deg[d], sp);
        atomicAdd(&g_cnt[d], 1);
    }
}

__global__ void k_dinv() {
    int i = blockIdx.x * blockDim.x + threadIdx.x;
    if (i < N_NODES) g_dinv[i] = rsqrtf(g_deg[i]);
}

__global__ void k_scan1() {
    __shared__ int s[SCAN_B];
    int b = blockIdx.x, tid = threadIdx.x;
    int i = b * SCAN_B + tid;
    int v = (i < N_NODES) ? g_cnt[i] : 0;
    s[tid] = v;
    __syncthreads();
    #pragma unroll
    for (int off = 1; off < SCAN_B; off <<= 1) {
        int t = (tid >= off) ? s[tid - off] : 0;
        __syncthreads();
        s[tid] += t;
        __syncthreads();
    }
    if (i < N_NODES) g_rowptr[i] = s[tid] - v;
    if (tid == SCAN_B - 1) g_part[b] = s[tid];
}

__global__ void k_scan2() {
    __shared__ int s[64];
    int tid = threadIdx.x;
    int v = (tid < NCHUNK) ? g_part[tid] : 0;
    s[tid] = v;
    __syncthreads();
    #pragma unroll
    for (int off = 1; off < 64; off <<= 1) {
        int t = (tid >= off) ? s[tid - off] : 0;
        __syncthreads();
        s[tid] += t;
        __syncthreads();
    }
    if (tid < NCHUNK) g_partscan[tid] = s[tid] - v;
    if (tid == NCHUNK - 1) g_rowptr[N_NODES] = s[tid];
}

__global__ void k_scan3() {
    int i = blockIdx.x * blockDim.x + threadIdx.x;
    if (i < N_NODES) {
        int v = g_rowptr[i] + g_partscan[i / SCAN_B];
        g_rowptr[i] = v;
        g_fill[i] = v;
    }
}

__global__ void k_place(const int* __restrict__ src,
                        const int* __restrict__ dst) {
    int i = blockIdx.x * blockDim.x + threadIdx.x;
    if (i < N_EDGES) {
        int s = src[i], d = dst[i];
        float w = g_dinv[s] * g_ew[i] * g_dinv[d];
        int pos = atomicAdd(&g_fill[d], 1);
        g_csr_src[pos] = s;
        g_csr_w[pos] = w;
    }
}

// convert x (fp32) -> g_xh (half)
__global__ void k_x2h(const float* __restrict__ x) {
    int i = blockIdx.x * blockDim.x + threadIdx.x;
    if (i < N_NODES * D_IN / 4) {
        float4 v = __ldg(&((const float4*)x)[i]);
        uint2 u;
        *(__half2*)&u.x = __floats2half2_rn(v.x, v.y);
        *(__half2*)&u.y = __floats2half2_rn(v.z, v.w);
        ((uint2*)g_xh)[i] = u;
    }
}

// ---------------- aggregation: warp per node, CSR gather over half rows ------
template <int DIM, bool OUT_FLOAT>
__device__ __forceinline__ void agg_half_body(const __half* __restrict__ src,
                                              __half* __restrict__ dsth,
                                              float* __restrict__ dstf,
                                              const float* __restrict__ bias) {
    int warp = (blockIdx.x * blockDim.x + threadIdx.x) >> 5;
    int lane = threadIdx.x & 31;
    if (warp >= N_NODES) return;
    constexpr int V = DIM / 128;   // uint2 (=4 halves) slots per lane

    int start = g_rowptr[warp];
    int end   = g_rowptr[warp + 1];
    float di = g_dinv[warp];
    float w0 = di * di;

    float2 acc[V][2];
    const uint2* sr = (const uint2*)(src + (size_t)warp * DIM);
    #pragma unroll
    for (int v = 0; v < V; v++) {
        uint2 u = __ldg(&sr[lane + 32 * v]);
        float2 f0 = __half22float2(*(__half2*)&u.x);
        float2 f1 = __half22float2(*(__half2*)&u.y);
        acc[v][0] = make_float2(w0 * f0.x, w0 * f0.y);
        acc[v][1] = make_float2(w0 * f1.x, w0 * f1.y);
    }

    int e = start;
    for (; e + 1 < end; e += 2) {
        int   s0 = g_csr_src[e],   s1 = g_csr_src[e + 1];
        float w1 = g_csr_w[e],     w2 = g_csr_w[e + 1];
        const uint2* r0 = (const uint2*)(src + (size_t)s0 * DIM);
        const uint2* r1 = (const uint2*)(src + (size_t)s1 * DIM);
        #pragma unroll
        for (int v = 0; v < V; v++) {
            uint2 a = __ldg(&r0[lane + 32 * v]);
            uint2 b = __ldg(&r1[lane + 32 * v]);
            float2 a0 = __half22float2(*(__half2*)&a.x);
            float2 a1 = __half22float2(*(__half2*)&a.y);
            float2 b0 = __half22float2(*(__half2*)&b.x);
            float2 b1 = __half22float2(*(__half2*)&b.y);
            acc[v][0].x += w1 * a0.x + w2 * b0.x;
            acc[v][0].y += w1 * a0.y + w2 * b0.y;
            acc[v][1].x += w1 * a1.x + w2 * b1.x;
            acc[v][1].y += w1 * a1.y + w2 * b1.y;
        }
    }
    if (e < end) {
        int s0 = g_csr_src[e];
        float w1 = g_csr_w[e];
        const uint2* r0 = (const uint2*)(src + (size_t)s0 * DIM);
        #pragma unroll
        for (int v = 0; v < V; v++) {
            uint2 a = __ldg(&r0[lane + 32 * v]);
            float2 a0 = __half22float2(*(__half2*)&a.x);
            float2 a1 = __half22float2(*(__half2*)&a.y);
            acc[v][0].x += w1 * a0.x; acc[v][0].y += w1 * a0.y;
            acc[v][1].x += w1 * a1.x; acc[v][1].y += w1 * a1.y;
        }
    }

    if (OUT_FLOAT) {
        float4* dr = (float4*)(dstf + (size_t)warp * DIM);
        #pragma unroll
        for (int v = 0; v < V; v++) {
            float4 b4 = __ldg(&((const float4*)bias)[lane + 32 * v]);
            dr[lane + 32 * v] = make_float4(acc[v][0].x + b4.x, acc[v][0].y + b4.y,
                                            acc[v][1].x + b4.z, acc[v][1].y + b4.w);
        }
    } else {
        uint2* dr = (uint2*)(dsth + (size_t)warp * DIM);
        #pragma unroll
        for (int v = 0; v < V; v++) {
            uint2 u;
            *(__half2*)&u.x = __floats2half2_rn(acc[v][0].x, acc[v][0].y);
            *(__half2*)&u.y = __floats2half2_rn(acc[v][1].x, acc[v][1].y);
            dr[lane + 32 * v] = u;
        }
    }
}

__global__ void k_agg_x() {
    agg_half_body<128, false>(g_xh, g_agg, nullptr, nullptr);
}
__global__ void k_agg_h() {
    agg_half_body<256, false>(g_h, g_agg, nullptr, nullptr);
}
__global__ void k_agg_out(float* __restrict__ out, const float* __restrict__ b3) {
    agg_half_body<128, true>(g_xw, nullptr, out, b3);
}

// ---------------- fp16 tensor-core GEMM (m16n8k16, fp32 accum) ---------------
__device__ __forceinline__ void mma_f16(float* c, const uint32_t* a, const uint32_t* b) {
    asm volatile(
        "mma.sync.aligned.m16n8k16.row.col.f32.f16.f16.f32 "
        "{%0,%1,%2,%3}, {%4,%5,%6,%7}, {%8,%9}, {%0,%1,%2,%3};\n"
        : "+f"(c[0]), "+f"(c[1]), "+f"(c[2]), "+f"(c[3])
        : "r"(a[0]), "r"(a[1]), "r"(a[2]), "r"(a[3]), "r"(b[0]), "r"(b[1]));
}

// C[M,N](half) = A[M,K](half) @ B[K,N](fp32->half); MODE 1: relu(+bias)
template <int MODE>
__device__ __forceinline__ void gemm_fp16(const __half* __restrict__ A,
                                          const float* __restrict__ B,
                                          const float* __restrict__ bias,
                                          __half* __restrict__ C,
                                          int M, int K, int N) {
    // packed k-pair (uint32 = 2 halves) tiles; strides chosen conflict-free
    __shared__ uint32_t As32[2][128][12];   // [m][kpair], 8 used, stride 12
    __shared__ uint32_t Bs32[2][8][136];    // [kpair][n], stride 136

    int tid  = threadIdx.x;
    int lane = tid & 31;
    int warp = tid >> 5;
    int gid  = lane >> 2;   // 0..7
    int tig  = lane & 3;    // 0..3
    int wm   = warp >> 2;   // 0..1
    int wn   = warp & 3;    // 0..3
    int row0 = blockIdx.x * 128;
    int col0 = blockIdx.y * 128;

    int arow  = tid >> 1;          // 0..127
    int apair = (tid & 1) * 4;     // uint32 index 0 or 4
    int kp    = tid >> 5;          // 0..7
    int nb    = lane * 4;          // 0..124

    float acc[4][4][4];
    #pragma unroll
    for (int mt = 0; mt < 4; mt++)
        #pragma unroll
        for (int nt = 0; nt < 4; nt++)
            #pragma unroll
            for (int r = 0; r < 4; r++) acc[mt][nt][r] = 0.f;

    // ---- load k-tile 0 ----
    {
        int gr = row0 + arow;
        uint4 ua = make_uint4(0, 0, 0, 0);
        if (gr < M) ua = *(const uint4*)(A + (size_t)gr * K + apair * 2);
        *(uint4*)&As32[0][arow][apair] = ua;

        int k0 = 2 * kp;
        float4 v0 = *(const float4*)(B + (size_t)k0 * N + col0 + nb);
        float4 v1 = *(const float4*)(B + (size_t)(k0 + 1) * N + col0 + nb);
        uint4 ub;
        *(__half2*)&ub.x = __floats2half2_rn(v0.x, v1.x);
        *(__half2*)&ub.y = __floats2half2_rn(v0.y, v1.y);
        *(__half2*)&ub.z = __floats2half2_rn(v0.z, v1.z);
        *(__half2*)&ub.w = __floats2half2_rn(v0.w, v1.w);
        *(uint4*)&Bs32[0][kp][nb] = ub;
    }
    __syncthreads();

    int ktiles = K >> 4;
    int p = 0;
    for (int t = 0; t < ktiles; t++) {
        uint4 av;
        float4 bv0, bv1;
        bool more = (t + 1 < ktiles);
        if (more) {
            int kb = (t + 1) << 4;
            int gr = row0 + arow;
            av = make_uint4(0, 0, 0, 0);
            if (gr < M) av = *(const uint4*)(A + (size_t)gr * K + kb + apair * 2);
            int k0 = kb + 2 * kp;
            bv0 = *(const float4*)(B + (size_t)k0 * N + col0 + nb);
            bv1 = *(const float4*)(B + (size_t)(k0 + 1) * N + col0 + nb);
        }

        uint32_t af[4][4], bf[4][2];
        #pragma unroll
        for (int mt = 0; mt < 4; mt++) {
            int r = wm * 64 + mt * 16 + gid;
            af[mt][0] = As32[p][r][tig];
            af[mt][1] = As32[p][r + 8][tig];
            af[mt][2] = As32[p][r][tig + 4];
            af[mt][3] = As32[p][r + 8][tig + 4];
        }
        #pragma unroll
        for (int nt = 0; nt < 4; nt++) {
            int n = wn * 32 + nt * 8 + gid;
            bf[nt][0] = Bs32[p][tig][n];
            bf[nt][1] = Bs32[p][tig + 4][n];
        }
        #pragma unroll
        for (int mt = 0; mt < 4; mt++)
            #pragma unroll
            for (int nt = 0; nt < 4; nt++)
                mma_f16(acc[mt][nt], af[mt], bf[nt]);

        if (more) {
            int q = p ^ 1;
            *(uint4*)&As32[q][arow][apair] = av;
            uint4 ub;
            *(__half2*)&ub.x = __floats2half2_rn(bv0.x, bv1.x);
            *(__half2*)&ub.y = __floats2half2_rn(bv0.y, bv1.y);
            *(__half2*)&ub.z = __floats2half2_rn(bv0.z, bv1.z);
            *(__half2*)&ub.w = __floats2half2_rn(bv0.w, bv1.w);
            *(uint4*)&Bs32[q][kp][nb] = ub;
        }
        __syncthreads();
        p ^= 1;
    }

    // ---- epilogue: write half2 pairs ----
    #pragma unroll
    for (int mt = 0; mt < 4; mt++) {
        #pragma unroll
        for (int h = 0; h < 2; h++) {
            int r = row0 + wm * 64 + mt * 16 + gid + h * 8;
            if (r < M) {
                #pragma unroll
                for (int nt = 0; nt < 4; nt++) {
                    int c = col0 + wn * 32 + nt * 8 + 2 * tig;
                    float v0 = acc[mt][nt][h * 2 + 0];
                    float v1 = acc[mt][nt][h * 2 + 1];
                    if (MODE == 1) {
                        v0 = fmaxf(v0 + __ldg(&bias[c]), 0.f);
                        v1 = fmaxf(v1 + __ldg(&bias[c + 1]), 0.f);
                    }
                    *(__half2*)(C + (size_t)r * N + c) = __floats2half2_rn(v0, v1);
                }
            }
        }
    }
}

__global__ __launch_bounds__(256) void k_gemm1(const float* __restrict__ W1,
                                               const float* __restrict__ b1) {
    gemm_fp16<1>(g_agg, W1, b1, g_h, N_NODES, D_IN, D_HID);
}
__global__ __launch_bounds__(256) void k_gemm2(const float* __restrict__ W2,
                                               const float* __restrict__ b2) {
    gemm_fp16<1>(g_agg, W2, b2, g_h, N_NODES, D_HID, D_HID);
}
__global__ __launch_bounds__(256) void k_gemm3(const float* __restrict__ W3) {
    gemm_fp16<0>(g_h, W3, nullptr, g_xw, N_NODES, D_HID, D_OUT);
}

// ---------------- launch -----------------------------------------------------
extern "C" void kernel_launch(void* const* d_in, const int* in_sizes, int n_in,
                              void* d_out, int out_size) {
    const float* x      = (const float*)d_in[0];
    const int*   ei     = (const int*)d_in[1];   // int32 (harness downcasts int64)
    const float* ew_raw = (const float*)d_in[2];
    const float* W1     = (const float*)d_in[3];
    const float* b1     = (const float*)d_in[4];
    const float* W2     = (const float*)d_in[5];
    const float* b2     = (const float*)d_in[6];
    const float* W3     = (const float*)d_in[7];
    const float* b3     = (const float*)d_in[8];
    float* out          = (float*)d_out;

    const int* src = ei;
    const int* dst = ei + N_EDGES;

    const int T = 256;
    int nb_nodes = (N_NODES + T - 1) / T;
    int nb_edges = (N_EDGES + T - 1) / T;
    int agg_blocks = (N_NODES * 32 + T - 1) / T;
    int gm = (N_NODES + 127) / 128;   // 391

    // prep: degrees + softplus + CSR (+ x -> half)
    k_init<<<nb_nodes, T>>>();
    k_edge_prep<<<nb_edges, T>>>(ew_raw, dst);
    k_x2h<<<(N_NODES * D_IN / 4 + T - 1) / T, T>>>(x);
    k_dinv<<<nb_nodes, T>>>();
    k_scan1<<<NCHUNK, SCAN_B>>>();
    k_scan2<<<1, 64>>>();
    k_scan3<<<nb_nodes, T>>>();
    k_place<<<nb_edges, T>>>(src, dst);

    // layer 1: agg(xh)[128] -> relu(@W1 + b1) -> g_h
    k_agg_x<<<agg_blocks, T>>>();
    k_gemm1<<<dim3(gm, 2), 256>>>(W1, b1);

    // layer 2: agg(g_h)[256] -> relu(@W2 + b2) -> g_h
    k_agg_h<<<agg_blocks, T>>>();
    k_gemm2<<<dim3(gm, 2), 256>>>(W2, b2);

    // layer 3: g_h @ W3 [->128] -> g_xw, then agg + b3 -> out (fp32)
    k_gemm3<<<dim3(gm, 1), 256>>>(W3);
    k_agg_out<<<agg_blocks, T>>>(out, b3);
}

// round 9
// speedup vs baseline: 4.9235x; 1.1480x over previous
#include <cuda_runtime.h>
#include <cuda_fp16.h>
#include <cstdint>

#define N_NODES 50000
#define N_EDGES 600000
#define D_IN 128
#define D_HID 256
#define D_OUT 128
#define SCAN_B 1024
#define NCHUNK ((N_NODES + SCAN_B - 1) / SCAN_B)   // 49

// ---------------- scratch (device globals; bound ONLY in device code) --------
__device__ float g_deg[N_NODES];
__device__ float g_dinv[N_NODES];
__device__ float g_ew[N_EDGES];
__device__ int   g_cnt[N_NODES];
__device__ int   g_rowptr[N_NODES + 1];
__device__ int   g_fill[N_NODES];
__device__ int   g_part[NCHUNK];
__device__ int   g_partscan[NCHUNK];
__device__ int   g_csr_src[N_EDGES];
__device__ float g_csr_w[N_EDGES];
__device__ __align__(256) __half g_xh[N_NODES * D_IN];
__device__ __align__(256) __half g_agg[N_NODES * D_HID];
__device__ __align__(256) __half g_h[N_NODES * D_HID];
__device__ __align__(256) __half g_xw[N_NODES * D_OUT];
// transposed half weights: Wt[n][k] = W[k][n]
__device__ __align__(256) __half g_w1t[D_HID * D_IN];    // [256][128]
__device__ __align__(256) __half g_w2t[D_HID * D_HID];   // [256][256]
__device__ __align__(256) __half g_w3t[D_OUT * D_HID];   // [128][256]

// ---------------- asm helpers ------------------------------------------------
__device__ __forceinline__ uint32_t smem_u32(const void* p) {
    uint32_t a;
    asm("{ .reg .u64 t; cvta.to.shared.u64 t, %1; cvt.u32.u64 %0, t; }"
        : "=r"(a) : "l"(p));
    return a;
}
__device__ __forceinline__ void ldsm4(uint32_t* r, uint32_t addr) {
    asm volatile("ldmatrix.sync.aligned.m8n8.x4.shared.b16 {%0,%1,%2,%3}, [%4];"
                 : "=r"(r[0]), "=r"(r[1]), "=r"(r[2]), "=r"(r[3]) : "r"(addr));
}
__device__ __forceinline__ void cpa16(uint32_t saddr, const void* g, bool pred) {
    int sz = pred ? 16 : 0;
    asm volatile("cp.async.ca.shared.global [%0], [%1], 16, %2;"
                 :: "r"(saddr), "l"(g), "r"(sz));
}
__device__ __forceinline__ void cpa_commit() {
    asm volatile("cp.async.commit_group;" ::: "memory");
}
template <int N>
__device__ __forceinline__ void cpa_wait() {
    asm volatile("cp.async.wait_group %0;" :: "n"(N) : "memory");
}
__device__ __forceinline__ void mma_f16(float* c, const uint32_t* a, const uint32_t* b) {
    asm volatile(
        "mma.sync.aligned.m16n8k16.row.col.f32.f16.f16.f32 "
        "{%0,%1,%2,%3}, {%4,%5,%6,%7}, {%8,%9}, {%0,%1,%2,%3};\n"
        : "+f"(c[0]), "+f"(c[1]), "+f"(c[2]), "+f"(c[3])
        : "r"(a[0]), "r"(a[1]), "r"(a[2]), "r"(a[3]), "r"(b[0]), "r"(b[1]));
}

// swizzled offset within a tile of 128B rows: chunk c (0..7, 16B each)
__device__ __forceinline__ uint32_t sw(int r, int c) {
    return (uint32_t)r * 128u + (uint32_t)((c ^ (r & 7)) << 4);
}

// ---------------- GEMM body: C[M,NTOT](h) = A[M,K](h) @ Bt[NTOT,K](h)^T ------
// block tile 64x128, 8 warps (2m x 4n), warp tile 32x32, k-tile 64, cp.async x2
template <int K, int NTOT, bool RELU>
__device__ __forceinline__ void gemm_body(const __half* __restrict__ A,
                                          const __half* __restrict__ Bt,
                                          const float* __restrict__ bias,
                                          __half* __restrict__ C) {
    __shared__ __align__(16) char sA[2][8192];    // 64 rows x 128B
    __shared__ __align__(16) char sB[2][16384];   // 128 rows x 128B

    int tid = threadIdx.x;
    int lane = tid & 31, warp = tid >> 5;
    int gid = lane >> 2, tig = lane & 3;
    int wm = warp >> 2, wn = warp & 3;
    int row0 = blockIdx.x * 64;
    int col0 = blockIdx.y * 128;

    uint32_t a_base = smem_u32(sA);
    uint32_t b_base = smem_u32(sB);

    float acc[2][4][4];
    #pragma unroll
    for (int mt = 0; mt < 2; mt++)
        #pragma unroll
        for (int nt = 0; nt < 4; nt++)
            #pragma unroll
            for (int q = 0; q < 4; q++) acc[mt][nt][q] = 0.f;

    constexpr int KT = K / 64;

    // ---- prologue: tile 0 ----
    {
        #pragma unroll
        for (int i = 0; i < 2; i++) {
            int idx = tid + i * 256, r = idx >> 3, c = idx & 7;
            int gr = row0 + r;
            cpa16(a_base + sw(r, c), A + (size_t)gr * K + c * 8, gr < N_NODES);
        }
        #pragma unroll
        for (int i = 0; i < 4; i++) {
            int idx = tid + i * 256, r = idx >> 3, c = idx & 7;
            cpa16(b_base + sw(r, c), Bt + (size_t)(col0 + r) * K + c * 8, true);
        }
        cpa_commit();
    }

    #pragma unroll
    for (int t = 0; t < KT; t++) {
        int buf = t & 1;
        if (t + 1 < KT) {
            int nb_ = (t + 1) & 1, kb = (t + 1) * 64;
            #pragma unroll
            for (int i = 0; i < 2; i++) {
                int idx = tid + i * 256, r = idx >> 3, c = idx & 7;
                int gr = row0 + r;
                cpa16(a_base + nb_ * 8192 + sw(r, c),
                      A + (size_t)gr * K + kb + c * 8, gr < N_NODES);
            }
            #pragma unroll
            for (int i = 0; i < 4; i++) {
                int idx = tid + i * 256, r = idx >> 3, c = idx & 7;
                cpa16(b_base + nb_ * 16384 + sw(r, c),
                      Bt + (size_t)(col0 + r) * K + kb + c * 8, true);
            }
            cpa_commit();
            cpa_wait<1>();
        } else {
            cpa_wait<0>();
        }
        __syncthreads();

        uint32_t ab = a_base + buf * 8192;
        uint32_t bb = b_base + buf * 16384;
        #pragma unroll
        for (int ks = 0; ks < 4; ks++) {
            int c0 = ks * 2;
            uint32_t af[2][4], bf[4][2];
            #pragma unroll
            for (int mt = 0; mt < 2; mt++) {
                int r = wm * 32 + mt * 16 + (lane & 15);
                int c = c0 + (lane >> 4);
                ldsm4(af[mt], ab + sw(r, c));
            }
            #pragma unroll
            for (int bg = 0; bg < 2; bg++) {
                int r = wn * 32 + bg * 16 + ((lane >> 4) << 3) + (lane & 7);
                int c = c0 + ((lane >> 3) & 1);
                uint32_t q[4];
                ldsm4(q, bb + sw(r, c));
                bf[bg * 2][0] = q[0]; bf[bg * 2][1] = q[1];
                bf[bg * 2 + 1][0] = q[2]; bf[bg * 2 + 1][1] = q[3];
            }
            #pragma unroll
            for (int mt = 0; mt < 2; mt++)
                #pragma unroll
                for (int nt = 0; nt < 4; nt++)
                    mma_f16(acc[mt][nt], af[mt], bf[nt]);
        }
        __syncthreads();
    }

    // ---- epilogue ----
    #pragma unroll
    for (int mt = 0; mt < 2; mt++) {
        #pragma unroll
        for (int h = 0; h < 2; h++) {
            int r = row0 + wm * 32 + mt * 16 + gid + h * 8;
            if (r < N_NODES) {
                #pragma unroll
                for (int nt = 0; nt < 4; nt++) {
                    int c = col0 + wn * 32 + nt * 8 + 2 * tig;
                    float v0 = acc[mt][nt][h * 2 + 0];
                    float v1 = acc[mt][nt][h * 2 + 1];
                    if (RELU) {
                        v0 = fmaxf(v0 + __ldg(&bias[c]), 0.f);
                        v1 = fmaxf(v1 + __ldg(&bias[c + 1]), 0.f);
                    }
                    *(__half2*)(C + (size_t)r * NTOT + c) = __floats2half2_rn(v0, v1);
                }
            }
        }
    }
}

// wrappers: globals bound in DEVICE code (host must never take their address)
__global__ __launch_bounds__(256) void k_gemm1(const float* __restrict__ b1) {
    gemm_body<128, 256, true>(g_agg, g_w1t, b1, g_h);
}
__global__ __launch_bounds__(256) void k_gemm2(const float* __restrict__ b2) {
    gemm_body<256, 256, true>(g_agg, g_w2t, b2, g_h);
}
__global__ __launch_bounds__(256) void k_gemm3() {
    gemm_body<256, 128, false>(g_h, g_w3t, nullptr, g_xw);
}

// ---------------- prep -------------------------------------------------------
__global__ void k_init() {
    int i = blockIdx.x * blockDim.x + threadIdx.x;
    if (i < N_NODES) { g_deg[i] = 1.0f; g_cnt[i] = 0; }
}

__global__ void k_edge_prep(const float* __restrict__ ew_raw,
                            const int* __restrict__ dst) {
    int i = blockIdx.x * blockDim.x + threadIdx.x;
    if (i < N_EDGES) {
        float w = ew_raw[i];
        float sp = fmaxf(w, 0.0f) + log1pf(expf(-fabsf(w)));
        g_ew[i] = sp;
        int d = dst[i];
        atomicAdd(&g_deg[d], sp);
        atomicAdd(&g_cnt[d], 1);
    }
}

// chunk scan + fused dinv
__global__ void k_scan1() {
    __shared__ int s[SCAN_B];
    int b = blockIdx.x, tid = threadIdx.x;
    int i = b * SCAN_B + tid;
    if (i < N_NODES) g_dinv[i] = rsqrtf(g_deg[i]);
    int v = (i < N_NODES) ? g_cnt[i] : 0;
    s[tid] = v;
    __syncthreads();
    #pragma unroll
    for (int off = 1; off < SCAN_B; off <<= 1) {
        int t = (tid >= off) ? s[tid - off] : 0;
        __syncthreads();
        s[tid] += t;
        __syncthreads();
    }
    if (i < N_NODES) g_rowptr[i] = s[tid] - v;
    if (tid == SCAN_B - 1) g_part[b] = s[tid];
}

__global__ void k_scan2() {
    __shared__ int s[64];
    int tid = threadIdx.x;
    int v = (tid < NCHUNK) ? g_part[tid] : 0;
    s[tid] = v;
    __syncthreads();
    #pragma unroll
    for (int off = 1; off < 64; off <<= 1) {
        int t = (tid >= off) ? s[tid - off] : 0;
        __syncthreads();
        s[tid] += t;
        __syncthreads();
    }
    if (tid < NCHUNK) g_partscan[tid] = s[tid] - v;
    if (tid == NCHUNK - 1) g_rowptr[N_NODES] = s[tid];
}

__global__ void k_scan3() {
    int i = blockIdx.x * blockDim.x + threadIdx.x;
    if (i < N_NODES) {
        int v = g_rowptr[i] + g_partscan[i / SCAN_B];
        g_rowptr[i] = v;
        g_fill[i] = v;
    }
}

__global__ void k_place(const int* __restrict__ src,
                        const int* __restrict__ dst) {
    int i = blockIdx.x * blockDim.x + threadIdx.x;
    if (i < N_EDGES) {
        int s = src[i], d = dst[i];
        float w = g_dinv[s] * g_ew[i] * g_dinv[d];
        int pos = atomicAdd(&g_fill[d], 1);
        g_csr_src[pos] = s;
        g_csr_w[pos] = w;
    }
}

__global__ void k_x2h(const float* __restrict__ x) {
    int i = blockIdx.x * blockDim.x + threadIdx.x;
    if (i < N_NODES * D_IN / 4) {
        float4 v = __ldg(&((const float4*)x)[i]);
        uint2 u;
        *(__half2*)&u.x = __floats2half2_rn(v.x, v.y);
        *(__half2*)&u.y = __floats2half2_rn(v.z, v.w);
        ((uint2*)g_xh)[i] = u;
    }
}

// transpose+convert all 3 weights to half [N,K]
__global__ void k_wt(const float* __restrict__ W1, const float* __restrict__ W2,
                     const float* __restrict__ W3) {
    int i = blockIdx.x * blockDim.x + threadIdx.x;
    if (i < D_HID * D_IN) {                         // W1t [256][128]
        int n = i / D_IN, k = i % D_IN;
        g_w1t[i] = __float2half_rn(W1[k * D_HID + n]);
    } else if (i < D_HID * D_IN + D_HID * D_HID) {  // W2t [256][256]
        int j = i - D_HID * D_IN;
        int n = j / D_HID, k = j % D_HID;
        g_w2t[j] = __float2half_rn(W2[k * D_HID + n]);
    } else if (i < D_HID * D_IN + D_HID * D_HID + D_OUT * D_HID) {  // W3t [128][256]
        int j = i - D_HID * D_IN - D_HID * D_HID;
        int n = j / D_HID, k = j % D_HID;
        g_w3t[j] = __float2half_rn(W3[k * D_OUT + n]);
    }
}

// ---------------- aggregation: warp per node, CSR gather (half) --------------
template <int DIM, bool OUT_FLOAT>
__device__ __forceinline__ void agg_half_body(const __half* __restrict__ src,
                                              __half* __restrict__ dsth,
                                              float* __restrict__ dstf,
                                              const float* __restrict__ bias) {
    int warp = (blockIdx.x * blockDim.x + threadIdx.x) >> 5;
    int lane = threadIdx.x & 31;
    if (warp >= N_NODES) return;
    constexpr int V = DIM / 128;

    int start = g_rowptr[warp];
    int end   = g_rowptr[warp + 1];
    float di = g_dinv[warp];
    float w0 = di * di;

    float2 acc[V][2];
    const uint2* sr = (const uint2*)(src + (size_t)warp * DIM);
    #pragma unroll
    for (int v = 0; v < V; v++) {
        uint2 u = __ldg(&sr[lane + 32 * v]);
        float2 f0 = __half22float2(*(__half2*)&u.x);
        float2 f1 = __half22float2(*(__half2*)&u.y);
        acc[v][0] = make_float2(w0 * f0.x, w0 * f0.y);
        acc[v][1] = make_float2(w0 * f1.x, w0 * f1.y);
    }

    int e = start;
    for (; e + 1 < end; e += 2) {
        int   s0 = g_csr_src[e],   s1 = g_csr_src[e + 1];
        float w1 = g_csr_w[e],     w2 = g_csr_w[e + 1];
        const uint2* r0 = (const uint2*)(src + (size_t)s0 * DIM);
        const uint2* r1 = (const uint2*)(src + (size_t)s1 * DIM);
        #pragma unroll
        for (int v = 0; v < V; v++) {
            uint2 a = __ldg(&r0[lane + 32 * v]);
            uint2 b = __ldg(&r1[lane + 32 * v]);
            float2 a0 = __half22float2(*(__half2*)&a.x);
            float2 a1 = __half22float2(*(__half2*)&a.y);
            float2 b0 = __half22float2(*(__half2*)&b.x);
            float2 b1 = __half22float2(*(__half2*)&b.y);
            acc[v][0].x += w1 * a0.x + w2 * b0.x;
            acc[v][0].y += w1 * a0.y + w2 * b0.y;
            acc[v][1].x += w1 * a1.x + w2 * b1.x;
            acc[v][1].y += w1 * a1.y + w2 * b1.y;
        }
    }
    if (e < end) {
        int s0 = g_csr_src[e];
        float w1 = g_csr_w[e];
        const uint2* r0 = (const uint2*)(src + (size_t)s0 * DIM);
        #pragma unroll
        for (int v = 0; v < V; v++) {
            uint2 a = __ldg(&r0[lane + 32 * v]);
            float2 a0 = __half22float2(*(__half2*)&a.x);
            float2 a1 = __half22float2(*(__half2*)&a.y);
            acc[v][0].x += w1 * a0.x; acc[v][0].y += w1 * a0.y;
            acc[v][1].x += w1 * a1.x; acc[v][1].y += w1 * a1.y;
        }
    }

    if (OUT_FLOAT) {
        float4* dr = (float4*)(dstf + (size_t)warp * DIM);
        #pragma unroll
        for (int v = 0; v < V; v++) {
            float4 b4 = __ldg(&((const float4*)bias)[lane + 32 * v]);
            dr[lane + 32 * v] = make_float4(acc[v][0].x + b4.x, acc[v][0].y + b4.y,
                                            acc[v][1].x + b4.z, acc[v][1].y + b4.w);
        }
    } else {
        uint2* dr = (uint2*)(dsth + (size_t)warp * DIM);
        #pragma unroll
        for (int v = 0; v < V; v++) {
            uint2 u;
            *(__half2*)&u.x = __floats2half2_rn(acc[v][0].x, acc[v][0].y);
            *(__half2*)&u.y = __floats2half2_rn(acc[v][1].x, acc[v][1].y);
            dr[lane + 32 * v] = u;
        }
    }
}

__global__ void k_agg_x() {
    agg_half_body<128, false>(g_xh, g_agg, nullptr, nullptr);
}
__global__ void k_agg_h() {
    agg_half_body<256, false>(g_h, g_agg, nullptr, nullptr);
}
__global__ void k_agg_out(float* __restrict__ out, const float* __restrict__ b3) {
    agg_half_body<128, true>(g_xw, nullptr, out, b3);
}

// ---------------- launch -----------------------------------------------------
extern "C" void kernel_launch(void* const* d_in, const int* in_sizes, int n_in,
                              void* d_out, int out_size) {
    const float* x      = (const float*)d_in[0];
    const int*   ei     = (const int*)d_in[1];   // int32 (harness downcasts int64)
    const float* ew_raw = (const float*)d_in[2];
    const float* W1     = (const float*)d_in[3];
    const float* b1     = (const float*)d_in[4];
    const float* W2     = (const float*)d_in[5];
    const float* b2     = (const float*)d_in[6];
    const float* W3     = (const float*)d_in[7];
    const float* b3     = (const float*)d_in[8];
    float* out          = (float*)d_out;

    const int* src = ei;
    const int* dst = ei + N_EDGES;

    const int T = 256;
    int nb_nodes = (N_NODES + T - 1) / T;
    int nb_edges = (N_EDGES + T - 1) / T;
    int agg_blocks = (N_NODES * 32 + T - 1) / T;
    int gm = (N_NODES + 63) / 64;   // 782

    // prep
    k_init<<<nb_nodes, T>>>();
    k_edge_prep<<<nb_edges, T>>>(ew_raw, dst);
    k_x2h<<<(N_NODES * D_IN / 4 + T - 1) / T, T>>>(x);
    k_wt<<<(D_HID * D_IN + D_HID * D_HID + D_OUT * D_HID + T - 1) / T, T>>>(W1, W2, W3);
    k_scan1<<<NCHUNK, SCAN_B>>>();
    k_scan2<<<1, 64>>>();
    k_scan3<<<nb_nodes, T>>>();
    k_place<<<nb_edges, T>>>(src, dst);

    // layer 1: agg(xh)[128] -> relu(@W1 + b1) -> g_h
    k_agg_x<<<agg_blocks, T>>>();
    k_gemm1<<<dim3(gm, 2), 256>>>(b1);

    // layer 2: agg(g_h)[256] -> relu(@W2 + b2) -> g_h
    k_agg_h<<<agg_blocks, T>>>();
    k_gemm2<<<dim3(gm, 2), 256>>>(b2);

    // layer 3: g_h @ W3 [->128] -> g_xw, then agg + b3 -> out (fp32)
    k_gemm3<<<dim3(gm, 1), 256>>>();
    k_agg_out<<<agg_blocks, T>>>(out, b3);
}

// round 10
// speedup vs baseline: 4.9937x; 1.0143x over previous
#include <cuda_runtime.h>
#include <cuda_fp16.h>
#include <cstdint>

#define N_NODES 50000
#define N_EDGES 600000
#define D_IN 128
#define D_HID 256
#define D_OUT 128
#define SCAN_B 1024
#define NCHUNK ((N_NODES + SCAN_B - 1) / SCAN_B)   // 49

// ---------------- scratch (device globals; bound ONLY in device code) --------
__device__ float g_deg[N_NODES];
__device__ float g_dinv[N_NODES];
__device__ float g_ew[N_EDGES];
__device__ int   g_cnt[N_NODES];
__device__ int   g_rowptr[N_NODES + 1];
__device__ int   g_fill[N_NODES];
__device__ int   g_part[NCHUNK];
__device__ int   g_partscan[NCHUNK];
__device__ int   g_csr_src[N_EDGES];
__device__ float g_csr_w[N_EDGES];
__device__ __align__(256) __half g_xh[N_NODES * D_IN];
__device__ __align__(256) __half g_agg[N_NODES * D_HID];
__device__ __align__(256) __half g_h[N_NODES * D_HID];
__device__ __align__(256) __half g_xw[N_NODES * D_OUT];
// transposed half weights: Wt[n][k] = W[k][n]
__device__ __align__(256) __half g_w1t[D_HID * D_IN];    // [256][128]
__device__ __align__(256) __half g_w2t[D_HID * D_HID];   // [256][256]
__device__ __align__(256) __half g_w3t[D_OUT * D_HID];   // [128][256]

// ---------------- asm helpers ------------------------------------------------
__device__ __forceinline__ uint32_t smem_u32(const void* p) {
    uint32_t a;
    asm("{ .reg .u64 t; cvta.to.shared.u64 t, %1; cvt.u32.u64 %0, t; }"
        : "=r"(a) : "l"(p));
    return a;
}
__device__ __forceinline__ void ldsm4(uint32_t* r, uint32_t addr) {
    asm volatile("ldmatrix.sync.aligned.m8n8.x4.shared.b16 {%0,%1,%2,%3}, [%4];"
                 : "=r"(r[0]), "=r"(r[1]), "=r"(r[2]), "=r"(r[3]) : "r"(addr));
}
__device__ __forceinline__ void cpa16(uint32_t saddr, const void* g, bool pred) {
    int sz = pred ? 16 : 0;
    asm volatile("cp.async.ca.shared.global [%0], [%1], 16, %2;"
                 :: "r"(saddr), "l"(g), "r"(sz));
}
__device__ __forceinline__ void cpa_commit() {
    asm volatile("cp.async.commit_group;" ::: "memory");
}
template <int N>
__device__ __forceinline__ void cpa_wait() {
    asm volatile("cp.async.wait_group %0;" :: "n"(N) : "memory");
}
__device__ __forceinline__ void mma_f16(float* c, const uint32_t* a, const uint32_t* b) {
    asm volatile(
        "mma.sync.aligned.m16n8k16.row.col.f32.f16.f16.f32 "
        "{%0,%1,%2,%3}, {%4,%5,%6,%7}, {%8,%9}, {%0,%1,%2,%3};\n"
        : "+f"(c[0]), "+f"(c[1]), "+f"(c[2]), "+f"(c[3])
        : "r"(a[0]), "r"(a[1]), "r"(a[2]), "r"(a[3]), "r"(b[0]), "r"(b[1]));
}

// swizzled offset within a tile of 128B rows: chunk c (0..7, 16B each)
__device__ __forceinline__ uint32_t sw(int r, int c) {
    return (uint32_t)r * 128u + (uint32_t)((c ^ (r & 7)) << 4);
}

// ---------------- GEMM body: C[M,NTOT](h) = A[M,K](h) @ Bt[NTOT,K](h)^T ------
// block tile 128x128, 8 warps (2m x 4n), warp tile 64x32, k-tile 64,
// cp.async double buffer, dynamic smem 64KB.
template <int K, int NTOT, bool RELU>
__device__ __forceinline__ void gemm_body(const __half* __restrict__ A,
                                          const __half* __restrict__ Bt,
                                          const float* __restrict__ bias,
                                          __half* __restrict__ C) {
    extern __shared__ __align__(16) char dsm[];
    // layout: A buf0 [0,16K), A buf1 [16K,32K), B buf0 [32K,48K), B buf1 [48K,64K)
    uint32_t a_base = smem_u32(dsm);
    uint32_t b_base = a_base + 32768;

    int tid = threadIdx.x;
    int lane = tid & 31, warp = tid >> 5;
    int gid = lane >> 2, tig = lane & 3;
    int wm = warp >> 2, wn = warp & 3;        // 2m x 4n
    int row0 = blockIdx.x * 128;
    int col0 = blockIdx.y * 128;

    float acc[4][4][4];
    #pragma unroll
    for (int mt = 0; mt < 4; mt++)
        #pragma unroll
        for (int nt = 0; nt < 4; nt++)
            #pragma unroll
            for (int q = 0; q < 4; q++) acc[mt][nt][q] = 0.f;

    constexpr int KT = K / 64;

    // ---- prologue: tile 0 (A: 128 rows x 8 chunks; B: 128 rows x 8 chunks) --
    {
        #pragma unroll
        for (int i = 0; i < 4; i++) {
            int idx = tid + i * 256, r = idx >> 3, c = idx & 7;
            int gr = row0 + r;
            cpa16(a_base + sw(r, c), A + (size_t)gr * K + c * 8, gr < N_NODES);
        }
        #pragma unroll
        for (int i = 0; i < 4; i++) {
            int idx = tid + i * 256, r = idx >> 3, c = idx & 7;
            cpa16(b_base + sw(r, c), Bt + (size_t)(col0 + r) * K + c * 8, true);
        }
        cpa_commit();
    }

    #pragma unroll
    for (int t = 0; t < KT; t++) {
        int buf = t & 1;
        if (t + 1 < KT) {
            int nb_ = (t + 1) & 1, kb = (t + 1) * 64;
            #pragma unroll
            for (int i = 0; i < 4; i++) {
                int idx = tid + i * 256, r = idx >> 3, c = idx & 7;
                int gr = row0 + r;
                cpa16(a_base + nb_ * 16384 + sw(r, c),
                      A + (size_t)gr * K + kb + c * 8, gr < N_NODES);
            }
            #pragma unroll
            for (int i = 0; i < 4; i++) {
                int idx = tid + i * 256, r = idx >> 3, c = idx & 7;
                cpa16(b_base + nb_ * 16384 + sw(r, c),
                      Bt + (size_t)(col0 + r) * K + kb + c * 8, true);
            }
            cpa_commit();
            cpa_wait<1>();
        } else {
            cpa_wait<0>();
        }
        __syncthreads();

        uint32_t ab = a_base + buf * 16384;
        uint32_t bb = b_base + buf * 16384;
        #pragma unroll
        for (int ks = 0; ks < 4; ks++) {
            int c0 = ks * 2;
            uint32_t af[4][4], bf[4][2];
            #pragma unroll
            for (int mt = 0; mt < 4; mt++) {
                int r = wm * 64 + mt * 16 + (lane & 15);
                int c = c0 + (lane >> 4);
                ldsm4(af[mt], ab + sw(r, c));
            }
            #pragma unroll
            for (int bg = 0; bg < 2; bg++) {
                int r = wn * 32 + bg * 16 + ((lane >> 4) << 3) + (lane & 7);
                int c = c0 + ((lane >> 3) & 1);
                uint32_t q[4];
                ldsm4(q, bb + sw(r, c));
                bf[bg * 2][0] = q[0]; bf[bg * 2][1] = q[1];
                bf[bg * 2 + 1][0] = q[2]; bf[bg * 2 + 1][1] = q[3];
            }
            #pragma unroll
            for (int mt = 0; mt < 4; mt++)
                #pragma unroll
                for (int nt = 0; nt < 4; nt++)
                    mma_f16(acc[mt][nt], af[mt], bf[nt]);
        }
        __syncthreads();
    }

    // ---- epilogue ----
    #pragma unroll
    for (int mt = 0; mt < 4; mt++) {
        #pragma unroll
        for (int h = 0; h < 2; h++) {
            int r = row0 + wm * 64 + mt * 16 + gid + h * 8;
            if (r < N_NODES) {
                #pragma unroll
                for (int nt = 0; nt < 4; nt++) {
                    int c = col0 + wn * 32 + nt * 8 + 2 * tig;
                    float v0 = acc[mt][nt][h * 2 + 0];
                    float v1 = acc[mt][nt][h * 2 + 1];
                    if (RELU) {
                        v0 = fmaxf(v0 + __ldg(&bias[c]), 0.f);
                        v1 = fmaxf(v1 + __ldg(&bias[c + 1]), 0.f);
                    }
                    *(__half2*)(C + (size_t)r * NTOT + c) = __floats2half2_rn(v0, v1);
                }
            }
        }
    }
}

// wrappers: globals bound in DEVICE code (host must never take their address)
__global__ __launch_bounds__(256) void k_gemm1(const float* __restrict__ b1) {
    gemm_body<128, 256, true>(g_agg, g_w1t, b1, g_h);
}
__global__ __launch_bounds__(256) void k_gemm2(const float* __restrict__ b2) {
    gemm_body<256, 256, true>(g_agg, g_w2t, b2, g_h);
}
__global__ __launch_bounds__(256) void k_gemm3() {
    gemm_body<256, 128, false>(g_h, g_w3t, nullptr, g_xw);
}

// ---------------- prep -------------------------------------------------------
// fused: x->half conversion, weight transpose+convert, deg/cnt init
#define XQ (N_NODES * D_IN / 4)                    // 1,600,000
#define WT1 (D_HID * D_IN)                         // 32768
#define WT2 (D_HID * D_HID)                        // 65536
#define WT3 (D_OUT * D_HID)                        // 32768
#define MISC_TOTAL (XQ + WT1 + WT2 + WT3 + N_NODES)

__global__ void k_misc(const float* __restrict__ x,
                       const float* __restrict__ W1,
                       const float* __restrict__ W2,
                       const float* __restrict__ W3) {
    int i = blockIdx.x * blockDim.x + threadIdx.x;
    if (i < XQ) {
        float4 v = __ldg(&((const float4*)x)[i]);
        uint2 u;
        *(__half2*)&u.x = __floats2half2_rn(v.x, v.y);
        *(__half2*)&u.y = __floats2half2_rn(v.z, v.w);
        ((uint2*)g_xh)[i] = u;
    } else if (i < XQ + WT1) {
        int j = i - XQ;
        int n = j / D_IN, k = j % D_IN;
        g_w1t[j] = __float2half_rn(W1[k * D_HID + n]);
    } else if (i < XQ + WT1 + WT2) {
        int j = i - XQ - WT1;
        int n = j / D_HID, k = j % D_HID;
        g_w2t[j] = __float2half_rn(W2[k * D_HID + n]);
    } else if (i < XQ + WT1 + WT2 + WT3) {
        int j = i - XQ - WT1 - WT2;
        int n = j / D_HID, k = j % D_HID;
        g_w3t[j] = __float2half_rn(W3[k * D_OUT + n]);
    } else if (i < MISC_TOTAL) {
        int j = i - XQ - WT1 - WT2 - WT3;
        g_deg[j] = 1.0f;
        g_cnt[j] = 0;
    }
}

__global__ void k_edge_prep(const float* __restrict__ ew_raw,
                            const int* __restrict__ dst) {
    int i = blockIdx.x * blockDim.x + threadIdx.x;
    if (i < N_EDGES) {
        float w = ew_raw[i];
        float sp = fmaxf(w, 0.0f) + log1pf(expf(-fabsf(w)));
        g_ew[i] = sp;
        int d = dst[i];
        atomicAdd(&g_deg[d], sp);
        atomicAdd(&g_cnt[d], 1);
    }
}

// chunk scan + fused dinv
__global__ void k_scan1() {
    __shared__ int s[SCAN_B];
    int b = blockIdx.x, tid = threadIdx.x;
    int i = b * SCAN_B + tid;
    if (i < N_NODES) g_dinv[i] = rsqrtf(g_deg[i]);
    int v = (i < N_NODES) ? g_cnt[i] : 0;
    s[tid] = v;
    __syncthreads();
    #pragma unroll
    for (int off = 1; off < SCAN_B; off <<= 1) {
        int t = (tid >= off) ? s[tid - off] : 0;
        __syncthreads();
        s[tid] += t;
        __syncthreads();
    }
    if (i < N_NODES) g_rowptr[i] = s[tid] - v;
    if (tid == SCAN_B - 1) g_part[b] = s[tid];
}

__global__ void k_scan2() {
    __shared__ int s[64];
    int tid = threadIdx.x;
    int v = (tid < NCHUNK) ? g_part[tid] : 0;
    s[tid] = v;
    __syncthreads();
    #pragma unroll
    for (int off = 1; off < 64; off <<= 1) {
        int t = (tid >= off) ? s[tid - off] : 0;
        __syncthreads();
        s[tid] += t;
        __syncthreads();
    }
    if (tid < NCHUNK) g_partscan[tid] = s[tid] - v;
    if (tid == NCHUNK - 1) g_rowptr[N_NODES] = s[tid];
}

__global__ void k_scan3() {
    int i = blockIdx.x * blockDim.x + threadIdx.x;
    if (i < N_NODES) {
        int v = g_rowptr[i] + g_partscan[i / SCAN_B];
        g_rowptr[i] = v;
        g_fill[i] = v;
    }
}

__global__ void k_place(const int* __restrict__ src,
                        const int* __restrict__ dst) {
    int i = blockIdx.x * blockDim.x + threadIdx.x;
    if (i < N_EDGES) {
        int s = src[i], d = dst[i];
        float w = g_dinv[s] * g_ew[i] * g_dinv[d];
        int pos = atomicAdd(&g_fill[d], 1);
        g_csr_src[pos] = s;
        g_csr_w[pos] = w;
    }
}

// ---------------- aggregation: warp per node, CSR gather (half) --------------
template <int DIM, bool OUT_FLOAT>
__device__ __forceinline__ void agg_half_body(const __half* __restrict__ src,
                                              __half* __restrict__ dsth,
                                              float* __restrict__ dstf,
                                              const float* __restrict__ bias) {
    int warp = (blockIdx.x * blockDim.x + threadIdx.x) >> 5;
    int lane = threadIdx.x & 31;
    if (warp >= N_NODES) return;
    constexpr int V = DIM / 128;

    int start = g_rowptr[warp];
    int end   = g_rowptr[warp + 1];
    float di = g_dinv[warp];
    float w0 = di * di;

    float2 acc[V][2];
    const uint2* sr = (const uint2*)(src + (size_t)warp * DIM);
    #pragma unroll
    for (int v = 0; v < V; v++) {
        uint2 u = __ldg(&sr[lane + 32 * v]);
        float2 f0 = __half22float2(*(__half2*)&u.x);
        float2 f1 = __half22float2(*(__half2*)&u.y);
        acc[v][0] = make_float2(w0 * f0.x, w0 * f0.y);
        acc[v][1] = make_float2(w0 * f1.x, w0 * f1.y);
    }

    int e = start;
    for (; e + 1 < end; e += 2) {
        int   s0 = g_csr_src[e],   s1 = g_csr_src[e + 1];
        float w1 = g_csr_w[e],     w2 = g_csr_w[e + 1];
        const uint2* r0 = (const uint2*)(src + (size_t)s0 * DIM);
        const uint2* r1 = (const uint2*)(src + (size_t)s1 * DIM);
        #pragma unroll
        for (int v = 0; v < V; v++) {
            uint2 a = __ldg(&r0[lane + 32 * v]);
            uint2 b = __ldg(&r1[lane + 32 * v]);
            float2 a0 = __half22float2(*(__half2*)&a.x);
            float2 a1 = __half22float2(*(__half2*)&a.y);
            float2 b0 = __half22float2(*(__half2*)&b.x);
            float2 b1 = __half22float2(*(__half2*)&b.y);
            acc[v][0].x += w1 * a0.x + w2 * b0.x;
            acc[v][0].y += w1 * a0.y + w2 * b0.y;
            acc[v][1].x += w1 * a1.x + w2 * b1.x;
            acc[v][1].y += w1 * a1.y + w2 * b1.y;
        }
    }
    if (e < end) {
        int s0 = g_csr_src[e];
        float w1 = g_csr_w[e];
        const uint2* r0 = (const uint2*)(src + (size_t)s0 * DIM);
        #pragma unroll
        for (int v = 0; v < V; v++) {
            uint2 a = __ldg(&r0[lane + 32 * v]);
            float2 a0 = __half22float2(*(__half2*)&a.x);
            float2 a1 = __half22float2(*(__half2*)&a.y);
            acc[v][0].x += w1 * a0.x; acc[v][0].y += w1 * a0.y;
            acc[v][1].x += w1 * a1.x; acc[v][1].y += w1 * a1.y;
        }
    }

    if (OUT_FLOAT) {
        float4* dr = (float4*)(dstf + (size_t)warp * DIM);
        #pragma unroll
        for (int v = 0; v < V; v++) {
            float4 b4 = __ldg(&((const float4*)bias)[lane + 32 * v]);
            dr[lane + 32 * v] = make_float4(acc[v][0].x + b4.x, acc[v][0].y + b4.y,
                                            acc[v][1].x + b4.z, acc[v][1].y + b4.w);
        }
    } else {
        uint2* dr = (uint2*)(dsth + (size_t)warp * DIM);
        #pragma unroll
        for (int v = 0; v < V; v++) {
            uint2 u;
            *(__half2*)&u.x = __floats2half2_rn(acc[v][0].x, acc[v][0].y);
            *(__half2*)&u.y = __floats2half2_rn(acc[v][1].x, acc[v][1].y);
            dr[lane + 32 * v] = u;
        }
    }
}

__global__ void k_agg_x() {
    agg_half_body<128, false>(g_xh, g_agg, nullptr, nullptr);
}
__global__ void k_agg_h() {
    agg_half_body<256, false>(g_h, g_agg, nullptr, nullptr);
}
__global__ void k_agg_out(float* __restrict__ out, const float* __restrict__ b3) {
    agg_half_body<128, true>(g_xw, nullptr, out, b3);
}

// ---------------- launch -----------------------------------------------------
extern "C" void kernel_launch(void* const* d_in, const int* in_sizes, int n_in,
                              void* d_out, int out_size) {
    const float* x      = (const float*)d_in[0];
    const int*   ei     = (const int*)d_in[1];   // int32 (harness downcasts int64)
    const float* ew_raw = (const float*)d_in[2];
    const float* W1     = (const float*)d_in[3];
    const float* b1     = (const float*)d_in[4];
    const float* W2     = (const float*)d_in[5];
    const float* b2     = (const float*)d_in[6];
    const float* W3     = (const float*)d_in[7];
    const float* b3     = (const float*)d_in[8];
    float* out          = (float*)d_out;

    const int* src = ei;
    const int* dst = ei + N_EDGES;

    const int T = 256;
    int nb_nodes = (N_NODES + T - 1) / T;
    int nb_edges = (N_EDGES + T - 1) / T;
    int agg_blocks = (N_NODES * 32 + T - 1) / T;
    int gm = (N_NODES + 127) / 128;   // 391

    const int GEMM_SMEM = 65536;   // 2x16K A + 2x16K B
    // Attribute set is not a stream op; persists from the first (uncaptured) call.
    cudaFuncSetAttribute(k_gemm1, cudaFuncAttributeMaxDynamicSharedMemorySize, GEMM_SMEM);
    cudaFuncSetAttribute(k_gemm2, cudaFuncAttributeMaxDynamicSharedMemorySize, GEMM_SMEM);
    cudaFuncSetAttribute(k_gemm3, cudaFuncAttributeMaxDynamicSharedMemorySize, GEMM_SMEM);

    // prep
    k_misc<<<(MISC_TOTAL + T - 1) / T, T>>>(x, W1, W2, W3);
    k_edge_prep<<<nb_edges, T>>>(ew_raw, dst);
    k_scan1<<<NCHUNK, SCAN_B>>>();
    k_scan2<<<1, 64>>>();
    k_scan3<<<nb_nodes, T>>>();
    k_place<<<nb_edges, T>>>(src, dst);

    // layer 1: agg(xh)[128] -> relu(@W1 + b1) -> g_h
    k_agg_x<<<agg_blocks, T>>>();
    k_gemm1<<<dim3(gm, 2), 256, GEMM_SMEM>>>(b1);

    // layer 2: agg(g_h)[256] -> relu(@W2 + b2) -> g_h
    k_agg_h<<<agg_blocks, T>>>();
    k_gemm2<<<dim3(gm, 2), 256, GEMM_SMEM>>>(b2);

    // layer 3: g_h @ W3 [->128] -> g_xw, then agg + b3 -> out (fp32)
    k_gemm3<<<dim3(gm, 1), 256, GEMM_SMEM>>>();
    k_agg_out<<<agg_blocks, T>>>(out, b3);
}

// round 11
// speedup vs baseline: 5.0939x; 1.0201x over previous
#include <cuda_runtime.h>
#include <cuda_fp16.h>
#include <cstdint>

#define N_NODES 50000
#define N_EDGES 600000
#define D_IN 128
#define D_HID 256
#define D_OUT 128
#define SCAN_B 1024
#define NCHUNK ((N_NODES + SCAN_B - 1) / SCAN_B)   // 49

// ---------------- scratch (device globals; bound ONLY in device code) --------
// NOTE: zero-initialized at module load. g_deg/g_cnt/g_tick are re-zeroed at
// the END of every run (after their last reader), so each graph replay starts
// from the identical state. No init kernel needed.
__device__ float g_deg[N_NODES];          // sum of softplus(in-edge w); +1 folded into dinv
__device__ float g_dinv[N_NODES];
__device__ float g_ew[N_EDGES];
__device__ int   g_cnt[N_NODES];
__device__ int   g_rowptr[N_NODES + 1];   // CHUNK-LOCAL exclusive prefix
__device__ int   g_fill[N_NODES];         // chunk-local cursors
__device__ int   g_part[NCHUNK];
__device__ int   g_partscan[NCHUNK];      // exclusive prefix of chunk totals
__device__ int   g_tick;                  // last-block ticket (self-resetting)
__device__ int   g_csr_src[N_EDGES];
__device__ float g_csr_w[N_EDGES];
__device__ __align__(256) __half g_xh[N_NODES * D_IN];
__device__ __align__(256) __half g_agg[N_NODES * D_HID];
__device__ __align__(256) __half g_h[N_NODES * D_HID];
__device__ __align__(256) __half g_xw[N_NODES * D_OUT];
__device__ __align__(256) __half g_w1t[D_HID * D_IN];    // [256][128]
__device__ __align__(256) __half g_w2t[D_HID * D_HID];   // [256][256]
__device__ __align__(256) __half g_w3t[D_OUT * D_HID];   // [128][256]

// ---------------- asm helpers ------------------------------------------------
__device__ __forceinline__ uint32_t smem_u32(const void* p) {
    uint32_t a;
    asm("{ .reg .u64 t; cvta.to.shared.u64 t, %1; cvt.u32.u64 %0, t; }"
        : "=r"(a) : "l"(p));
    return a;
}
__device__ __forceinline__ void ldsm4(uint32_t* r, uint32_t addr) {
    asm volatile("ldmatrix.sync.aligned.m8n8.x4.shared.b16 {%0,%1,%2,%3}, [%4];"
                 : "=r"(r[0]), "=r"(r[1]), "=r"(r[2]), "=r"(r[3]) : "r"(addr));
}
__device__ __forceinline__ void cpa16(uint32_t saddr, const void* g, bool pred) {
    int sz = pred ? 16 : 0;
    asm volatile("cp.async.ca.shared.global [%0], [%1], 16, %2;"
                 :: "r"(saddr), "l"(g), "r"(sz));
}
__device__ __forceinline__ void cpa_commit() {
    asm volatile("cp.async.commit_group;" ::: "memory");
}
template <int N>
__device__ __forceinline__ void cpa_wait() {
    asm volatile("cp.async.wait_group %0;" :: "n"(N) : "memory");
}
__device__ __forceinline__ void mma_f16(float* c, const uint32_t* a, const uint32_t* b) {
    asm volatile(
        "mma.sync.aligned.m16n8k16.row.col.f32.f16.f16.f32 "
        "{%0,%1,%2,%3}, {%4,%5,%6,%7}, {%8,%9}, {%0,%1,%2,%3};\n"
        : "+f"(c[0]), "+f"(c[1]), "+f"(c[2]), "+f"(c[3])
        : "r"(a[0]), "r"(a[1]), "r"(a[2]), "r"(a[3]), "r"(b[0]), "r"(b[1]));
}
__device__ __forceinline__ uint32_t sw(int r, int c) {
    return (uint32_t)r * 128u + (uint32_t)((c ^ (r & 7)) << 4);
}

// ---------------- GEMM body (unchanged from R10) -----------------------------
template <int K, int NTOT, bool RELU>
__device__ __forceinline__ void gemm_body(const __half* __restrict__ A,
                                          const __half* __restrict__ Bt,
                                          const float* __restrict__ bias,
                                          __half* __restrict__ C) {
    extern __shared__ __align__(16) char dsm[];
    uint32_t a_base = smem_u32(dsm);
    uint32_t b_base = a_base + 32768;

    int tid = threadIdx.x;
    int lane = tid & 31, warp = tid >> 5;
    int gid = lane >> 2, tig = lane & 3;
    int wm = warp >> 2, wn = warp & 3;
    int row0 = blockIdx.x * 128;
    int col0 = blockIdx.y * 128;

    float acc[4][4][4];
    #pragma unroll
    for (int mt = 0; mt < 4; mt++)
        #pragma unroll
        for (int nt = 0; nt < 4; nt++)
            #pragma unroll
            for (int q = 0; q < 4; q++) acc[mt][nt][q] = 0.f;

    constexpr int KT = K / 64;

    {
        #pragma unroll
        for (int i = 0; i < 4; i++) {
            int idx = tid + i * 256, r = idx >> 3, c = idx & 7;
            int gr = row0 + r;
            cpa16(a_base + sw(r, c), A + (size_t)gr * K + c * 8, gr < N_NODES);
        }
        #pragma unroll
        for (int i = 0; i < 4; i++) {
            int idx = tid + i * 256, r = idx >> 3, c = idx & 7;
            cpa16(b_base + sw(r, c), Bt + (size_t)(col0 + r) * K + c * 8, true);
        }
        cpa_commit();
    }

    #pragma unroll
    for (int t = 0; t < KT; t++) {
        int buf = t & 1;
        if (t + 1 < KT) {
            int nb_ = (t + 1) & 1, kb = (t + 1) * 64;
            #pragma unroll
            for (int i = 0; i < 4; i++) {
                int idx = tid + i * 256, r = idx >> 3, c = idx & 7;
                int gr = row0 + r;
                cpa16(a_base + nb_ * 16384 + sw(r, c),
                      A + (size_t)gr * K + kb + c * 8, gr < N_NODES);
            }
            #pragma unroll
            for (int i = 0; i < 4; i++) {
                int idx = tid + i * 256, r = idx >> 3, c = idx & 7;
                cpa16(b_base + nb_ * 16384 + sw(r, c),
                      Bt + (size_t)(col0 + r) * K + kb + c * 8, true);
            }
            cpa_commit();
            cpa_wait<1>();
        } else {
            cpa_wait<0>();
        }
        __syncthreads();

        uint32_t ab = a_base + buf * 16384;
        uint32_t bb = b_base + buf * 16384;
        #pragma unroll
        for (int ks = 0; ks < 4; ks++) {
            int c0 = ks * 2;
            uint32_t af[4][4], bf[4][2];
            #pragma unroll
            for (int mt = 0; mt < 4; mt++) {
                int r = wm * 64 + mt * 16 + (lane & 15);
                int c = c0 + (lane >> 4);
                ldsm4(af[mt], ab + sw(r, c));
            }
            #pragma unroll
            for (int bg = 0; bg < 2; bg++) {
                int r = wn * 32 + bg * 16 + ((lane >> 4) << 3) + (lane & 7);
                int c = c0 + ((lane >> 3) & 1);
                uint32_t q[4];
                ldsm4(q, bb + sw(r, c));
                bf[bg * 2][0] = q[0]; bf[bg * 2][1] = q[1];
                bf[bg * 2 + 1][0] = q[2]; bf[bg * 2 + 1][1] = q[3];
            }
            #pragma unroll
            for (int mt = 0; mt < 4; mt++)
                #pragma unroll
                for (int nt = 0; nt < 4; nt++)
                    mma_f16(acc[mt][nt], af[mt], bf[nt]);
        }
        __syncthreads();
    }

    #pragma unroll
    for (int mt = 0; mt < 4; mt++) {
        #pragma unroll
        for (int h = 0; h < 2; h++) {
            int r = row0 + wm * 64 + mt * 16 + gid + h * 8;
            if (r < N_NODES) {
                #pragma unroll
                for (int nt = 0; nt < 4; nt++) {
                    int c = col0 + wn * 32 + nt * 8 + 2 * tig;
                    float v0 = acc[mt][nt][h * 2 + 0];
                    float v1 = acc[mt][nt][h * 2 + 1];
                    if (RELU) {
                        v0 = fmaxf(v0 + __ldg(&bias[c]), 0.f);
                        v1 = fmaxf(v1 + __ldg(&bias[c + 1]), 0.f);
                    }
                    *(__half2*)(C + (size_t)r * NTOT + c) = __floats2half2_rn(v0, v1);
                }
            }
        }
    }
}

__global__ __launch_bounds__(256) void k_gemm1(const float* __restrict__ b1) {
    gemm_body<128, 256, true>(g_agg, g_w1t, b1, g_h);
}
__global__ __launch_bounds__(256) void k_gemm2(const float* __restrict__ b2) {
    gemm_body<256, 256, true>(g_agg, g_w2t, b2, g_h);
}
__global__ __launch_bounds__(256) void k_gemm3() {
    gemm_body<256, 128, false>(g_h, g_w3t, nullptr, g_xw);
}

// ---------------- fused prep: edge softplus+deg/cnt, x->half, Wt -------------
#define XQ (N_NODES * D_IN / 4)                    // 1,600,000
#define WT1 (D_HID * D_IN)
#define WT2 (D_HID * D_HID)
#define WT3 (D_OUT * D_HID)
#define PREP_TOTAL (N_EDGES + XQ + WT1 + WT2 + WT3)

__global__ void k_prep(const float* __restrict__ ew_raw,
                       const int* __restrict__ dst,
                       const float* __restrict__ x,
                       const float* __restrict__ W1,
                       const float* __restrict__ W2,
                       const float* __restrict__ W3) {
    int i = blockIdx.x * blockDim.x + threadIdx.x;
    if (i < N_EDGES) {   // edge range first: atomics on the critical path
        float w = ew_raw[i];
        float sp = fmaxf(w, 0.0f) + log1pf(expf(-fabsf(w)));
        g_ew[i] = sp;
        int d = dst[i];
        atomicAdd(&g_deg[d], sp);       // g_deg zeroed by previous run / load
        atomicAdd(&g_cnt[d], 1);
        return;
    }
    int j = i - N_EDGES;
    if (j < XQ) {
        float4 v = __ldg(&((const float4*)x)[j]);
        uint2 u;
        *(__half2*)&u.x = __floats2half2_rn(v.x, v.y);
        *(__half2*)&u.y = __floats2half2_rn(v.z, v.w);
        ((uint2*)g_xh)[j] = u;
        return;
    }
    j -= XQ;
    if (j < WT1) {
        int n = j / D_IN, k = j % D_IN;
        g_w1t[j] = __float2half_rn(W1[k * D_HID + n]);
        return;
    }
    j -= WT1;
    if (j < WT2) {
        int n = j / D_HID, k = j % D_HID;
        g_w2t[j] = __float2half_rn(W2[k * D_HID + n]);
        return;
    }
    j -= WT2;
    if (j < WT3) {
        int n = j / D_HID, k = j % D_HID;
        g_w3t[j] = __float2half_rn(W3[k * D_OUT + n]);
    }
}

// ---------------- scan: chunk scans + dinv + last-block partial scan ---------
__global__ void k_scan() {
    __shared__ int s[SCAN_B];
    __shared__ bool isLast;
    int b = blockIdx.x, tid = threadIdx.x;
    int i = b * SCAN_B + tid;
    if (i < N_NODES) g_dinv[i] = rsqrtf(g_deg[i] + 1.0f);  // +1 = self-loop
    int v = (i < N_NODES) ? g_cnt[i] : 0;
    s[tid] = v;
    __syncthreads();
    #pragma unroll
    for (int off = 1; off < SCAN_B; off <<= 1) {
        int t = (tid >= off) ? s[tid - off] : 0;
        __syncthreads();
        s[tid] += t;
        __syncthreads();
    }
    int excl = s[tid] - v;                 // chunk-local exclusive
    if (i < N_NODES) { g_rowptr[i] = excl; g_fill[i] = excl; }
    if (i == N_NODES - 1) g_rowptr[N_NODES] = s[tid];   // chunk-local inclusive
    if (tid == SCAN_B - 1) g_part[b] = s[tid];

    __threadfence();
    __syncthreads();
    if (tid == 0) isLast = (atomicAdd(&g_tick, 1) == NCHUNK - 1);
    __syncthreads();
    if (!isLast) return;
    __threadfence();   // acquire: other blocks' g_part writes

    int v2 = (tid < NCHUNK) ? g_part[tid] : 0;
    s[tid] = (tid < 64) ? v2 : 0;
    __syncthreads();
    #pragma unroll
    for (int off = 1; off < 64; off <<= 1) {
        int t = (tid >= off && tid < 64) ? s[tid - off] : 0;
        __syncthreads();
        if (tid < 64) s[tid] += t;
        __syncthreads();
    }
    if (tid < NCHUNK) g_partscan[tid] = s[tid] - v2;   // exclusive chunk prefix
    if (tid == 0) g_tick = 0;                          // self-reset for next run
}

// ---------------- place + deferred cleanup -----------------------------------
__global__ void k_place(const int* __restrict__ src,
                        const int* __restrict__ dst) {
    int i = blockIdx.x * blockDim.x + threadIdx.x;
    if (i < N_EDGES) {
        int s = src[i], d = dst[i];
        float w = g_dinv[s] * g_ew[i] * g_dinv[d];
        int pos = atomicAdd(&g_fill[d], 1) + g_partscan[d >> 10];
        g_csr_src[pos] = s;
        g_csr_w[pos] = w;
    }
    if (i < N_NODES) { g_deg[i] = 0.0f; g_cnt[i] = 0; }  // reset for next replay
}

// ---------------- aggregation: warp per node, CSR gather (half) --------------
template <int DIM, bool OUT_FLOAT>
__device__ __forceinline__ void agg_half_body(const __half* __restrict__ src,
                                              __half* __restrict__ dsth,
                                              float* __restrict__ dstf,
                                              const float* __restrict__ bias) {
    int warp = (blockIdx.x * blockDim.x + threadIdx.x) >> 5;
    int lane = threadIdx.x & 31;
    if (warp >= N_NODES) return;
    constexpr int V = DIM / 128;

    int start = g_rowptr[warp] + g_partscan[warp >> 10];
    int end   = g_rowptr[warp + 1] + g_partscan[(warp + 1) >> 10];
    float di = g_dinv[warp];
    float w0 = di * di;

    float2 acc[V][2];
    const uint2* sr = (const uint2*)(src + (size_t)warp * DIM);
    #pragma unroll
    for (int v = 0; v < V; v++) {
        uint2 u = __ldg(&sr[lane + 32 * v]);
        float2 f0 = __half22float2(*(__half2*)&u.x);
        float2 f1 = __half22float2(*(__half2*)&u.y);
        acc[v][0] = make_float2(w0 * f0.x, w0 * f0.y);
        acc[v][1] = make_float2(w0 * f1.x, w0 * f1.y);
    }

    int e = start;
    for (; e + 1 < end; e += 2) {
        int   s0 = g_csr_src[e],   s1 = g_csr_src[e + 1];
        float w1 = g_csr_w[e],     w2 = g_csr_w[e + 1];
        const uint2* r0 = (const uint2*)(src + (size_t)s0 * DIM);
        const uint2* r1 = (const uint2*)(src + (size_t)s1 * DIM);
        #pragma unroll
        for (int v = 0; v < V; v++) {
            uint2 a = __ldg(&r0[lane + 32 * v]);
            uint2 b = __ldg(&r1[lane + 32 * v]);
            float2 a0 = __half22float2(*(__half2*)&a.x);
            float2 a1 = __half22float2(*(__half2*)&a.y);
            float2 b0 = __half22float2(*(__half2*)&b.x);
            float2 b1 = __half22float2(*(__half2*)&b.y);
            acc[v][0].x += w1 * a0.x + w2 * b0.x;
            acc[v][0].y += w1 * a0.y + w2 * b0.y;
            acc[v][1].x += w1 * a1.x + w2 * b1.x;
            acc[v][1].y += w1 * a1.y + w2 * b1.y;
        }
    }
    if (e < end) {
        int s0 = g_csr_src[e];
        float w1 = g_csr_w[e];
        const uint2* r0 = (const uint2*)(src + (size_t)s0 * DIM);
        #pragma unroll
        for (int v = 0; v < V; v++) {
            uint2 a = __ldg(&r0[lane + 32 * v]);
            float2 a0 = __half22float2(*(__half2*)&a.x);
            float2 a1 = __half22float2(*(__half2*)&a.y);
            acc[v][0].x += w1 * a0.x; acc[v][0].y += w1 * a0.y;
            acc[v][1].x += w1 * a1.x; acc[v][1].y += w1 * a1.y;
        }
    }

    if (OUT_FLOAT) {
        float4* dr = (float4*)(dstf + (size_t)warp * DIM);
        #pragma unroll
        for (int v = 0; v < V; v++) {
            float4 b4 = __ldg(&((const float4*)bias)[lane + 32 * v]);
            dr[lane + 32 * v] = make_float4(acc[v][0].x + b4.x, acc[v][0].y + b4.y,
                                            acc[v][1].x + b4.z, acc[v][1].y + b4.w);
        }
    } else {
        uint2* dr = (uint2*)(dsth + (size_t)warp * DIM);
        #pragma unroll
        for (int v = 0; v < V; v++) {
            uint2 u;
            *(__half2*)&u.x = __floats2half2_rn(acc[v][0].x, acc[v][0].y);
            *(__half2*)&u.y = __floats2half2_rn(acc[v][1].x, acc[v][1].y);
            dr[lane + 32 * v] = u;
        }
    }
}

__global__ void k_agg_x() {
    agg_half_body<128, false>(g_xh, g_agg, nullptr, nullptr);
}
__global__ void k_agg_h() {
    agg_half_body<256, false>(g_h, g_agg, nullptr, nullptr);
}
__global__ void k_agg_out(float* __restrict__ out, const float* __restrict__ b3) {
    agg_half_body<128, true>(g_xw, nullptr, out, b3);
}

// ---------------- launch -----------------------------------------------------
extern "C" void kernel_launch(void* const* d_in, const int* in_sizes, int n_in,
                              void* d_out, int out_size) {
    const float* x      = (const float*)d_in[0];
    const int*   ei     = (const int*)d_in[1];   // int32 (harness downcasts int64)
    const float* ew_raw = (const float*)d_in[2];
    const float* W1     = (const float*)d_in[3];
    const float* b1     = (const float*)d_in[4];
    const float* W2     = (const float*)d_in[5];
    const float* b2     = (const float*)d_in[6];
    const float* W3     = (const float*)d_in[7];
    const float* b3     = (const float*)d_in[8];
    float* out          = (float*)d_out;

    const int* src = ei;
    const int* dst = ei + N_EDGES;

    const int T = 256;
    int nb_edges = (N_EDGES + T - 1) / T;
    int agg_blocks = (N_NODES * 32 + T - 1) / T;
    int gm = (N_NODES + 127) / 128;   // 391

    const int GEMM_SMEM = 65536;
    cudaFuncSetAttribute(k_gemm1, cudaFuncAttributeMaxDynamicSharedMemorySize, GEMM_SMEM);
    cudaFuncSetAttribute(k_gemm2, cudaFuncAttributeMaxDynamicSharedMemorySize, GEMM_SMEM);
    cudaFuncSetAttribute(k_gemm3, cudaFuncAttributeMaxDynamicSharedMemorySize, GEMM_SMEM);

    // prep (fused): edge softplus + deg/cnt atomics, x->half, weight transposes
    k_prep<<<(PREP_TOTAL + T - 1) / T, T>>>(ew_raw, dst, x, W1, W2, W3);
    // scan (fused): chunk scans + dinv + last-block partial scan
    k_scan<<<NCHUNK, SCAN_B>>>();
    // CSR place (+ deferred zeroing of deg/cnt for next replay)
    k_place<<<nb_edges, T>>>(src, dst);

    // layer 1: agg(xh)[128] -> relu(@W1 + b1) -> g_h
    k_agg_x<<<agg_blocks, T>>>();
    k_gemm1<<<dim3(gm, 2), 256, GEMM_SMEM>>>(b1);

    // layer 2: agg(g_h)[256] -> relu(@W2 + b2) -> g_h
    k_agg_h<<<agg_blocks, T>>>();
    k_gemm2<<<dim3(gm, 2), 256, GEMM_SMEM>>>(b2);

    // layer 3: g_h @ W3 [->128] -> g_xw, then agg + b3 -> out (fp32)
    k_gemm3<<<dim3(gm, 1), 256, GEMM_SMEM>>>();
    k_agg_out<<<agg_blocks, T>>>(out, b3);
}

// round 12
// speedup vs baseline: 5.2000x; 1.0208x over previous
#include <cuda_runtime.h>
#include <cuda_fp16.h>
#include <cstdint>

#define N_NODES 50000
#define N_EDGES 600000
#define D_IN 128
#define D_HID 256
#define D_OUT 128
#define SCAN_B 1024
#define NCHUNK ((N_NODES + SCAN_B - 1) / SCAN_B)   // 49

// ---------------- scratch (device globals; bound ONLY in device code) --------
// Zero-initialized at module load; g_deg/g_cnt/g_tick re-zeroed at the END of
// every run (after last reader) so each graph replay starts identically.
__device__ float g_deg[N_NODES];
__device__ float g_dinv[N_NODES];
__device__ float g_ew[N_EDGES];
__device__ int   g_cnt[N_NODES];
__device__ int   g_rowptr[N_NODES + 1];   // chunk-local exclusive prefix
__device__ int   g_fill[N_NODES];
__device__ int   g_part[NCHUNK];
__device__ int   g_partscan[NCHUNK];
__device__ int   g_tick;
__device__ int   g_csr_src[N_EDGES];
__device__ unsigned int g_csr_wh[N_EDGES];   // packed half2 {w,w}
__device__ __align__(256) __half g_xh[N_NODES * D_IN];
__device__ __align__(256) __half g_agg[N_NODES * D_HID];
__device__ __align__(256) __half g_h[N_NODES * D_HID];
__device__ __align__(256) __half g_xw[N_NODES * D_OUT];
__device__ __align__(256) __half g_w1t[D_HID * D_IN];
__device__ __align__(256) __half g_w2t[D_HID * D_HID];
__device__ __align__(256) __half g_w3t[D_OUT * D_HID];

// ---------------- asm helpers ------------------------------------------------
__device__ __forceinline__ uint32_t smem_u32(const void* p) {
    uint32_t a;
    asm("{ .reg .u64 t; cvta.to.shared.u64 t, %1; cvt.u32.u64 %0, t; }"
        : "=r"(a) : "l"(p));
    return a;
}
__device__ __forceinline__ void ldsm4(uint32_t* r, uint32_t addr) {
    asm volatile("ldmatrix.sync.aligned.m8n8.x4.shared.b16 {%0,%1,%2,%3}, [%4];"
                 : "=r"(r[0]), "=r"(r[1]), "=r"(r[2]), "=r"(r[3]) : "r"(addr));
}
__device__ __forceinline__ void cpa16(uint32_t saddr, const void* g, bool pred) {
    int sz = pred ? 16 : 0;
    asm volatile("cp.async.ca.shared.global [%0], [%1], 16, %2;"
                 :: "r"(saddr), "l"(g), "r"(sz));
}
__device__ __forceinline__ void cpa_commit() {
    asm volatile("cp.async.commit_group;" ::: "memory");
}
template <int N>
__device__ __forceinline__ void cpa_wait() {
    asm volatile("cp.async.wait_group %0;" :: "n"(N) : "memory");
}
__device__ __forceinline__ void mma_f16(float* c, const uint32_t* a, const uint32_t* b) {
    asm volatile(
        "mma.sync.aligned.m16n8k16.row.col.f32.f16.f16.f32 "
        "{%0,%1,%2,%3}, {%4,%5,%6,%7}, {%8,%9}, {%0,%1,%2,%3};\n"
        : "+f"(c[0]), "+f"(c[1]), "+f"(c[2]), "+f"(c[3])
        : "r"(a[0]), "r"(a[1]), "r"(a[2]), "r"(a[3]), "r"(b[0]), "r"(b[1]));
}
__device__ __forceinline__ uint32_t sw(int r, int c) {
    return (uint32_t)r * 128u + (uint32_t)((c ^ (r & 7)) << 4);
}
__device__ __forceinline__ __half2 u2h2(unsigned int u) {
    __half2 h; *(unsigned int*)&h = u; return h;
}

// ---------------- GEMM body (unchanged; proven) ------------------------------
template <int K, int NTOT, bool RELU>
__device__ __forceinline__ void gemm_body(const __half* __restrict__ A,
                                          const __half* __restrict__ Bt,
                                          const float* __restrict__ bias,
                                          __half* __restrict__ C) {
    extern __shared__ __align__(16) char dsm[];
    uint32_t a_base = smem_u32(dsm);
    uint32_t b_base = a_base + 32768;

    int tid = threadIdx.x;
    int lane = tid & 31, warp = tid >> 5;
    int gid = lane >> 2, tig = lane & 3;
    int wm = warp >> 2, wn = warp & 3;
    int row0 = blockIdx.x * 128;
    int col0 = blockIdx.y * 128;

    float acc[4][4][4];
    #pragma unroll
    for (int mt = 0; mt < 4; mt++)
        #pragma unroll
        for (int nt = 0; nt < 4; nt++)
            #pragma unroll
            for (int q = 0; q < 4; q++) acc[mt][nt][q] = 0.f;

    constexpr int KT = K / 64;

    {
        #pragma unroll
        for (int i = 0; i < 4; i++) {
            int idx = tid + i * 256, r = idx >> 3, c = idx & 7;
            int gr = row0 + r;
            cpa16(a_base + sw(r, c), A + (size_t)gr * K + c * 8, gr < N_NODES);
        }
        #pragma unroll
        for (int i = 0; i < 4; i++) {
            int idx = tid + i * 256, r = idx >> 3, c = idx & 7;
            cpa16(b_base + sw(r, c), Bt + (size_t)(col0 + r) * K + c * 8, true);
        }
        cpa_commit();
    }

    #pragma unroll
    for (int t = 0; t < KT; t++) {
        int buf = t & 1;
        if (t + 1 < KT) {
            int nb_ = (t + 1) & 1, kb = (t + 1) * 64;
            #pragma unroll
            for (int i = 0; i < 4; i++) {
                int idx = tid + i * 256, r = idx >> 3, c = idx & 7;
                int gr = row0 + r;
                cpa16(a_base + nb_ * 16384 + sw(r, c),
                      A + (size_t)gr * K + kb + c * 8, gr < N_NODES);
            }
            #pragma unroll
            for (int i = 0; i < 4; i++) {
                int idx = tid + i * 256, r = idx >> 3, c = idx & 7;
                cpa16(b_base + nb_ * 16384 + sw(r, c),
                      Bt + (size_t)(col0 + r) * K + kb + c * 8, true);
            }
            cpa_commit();
            cpa_wait<1>();
        } else {
            cpa_wait<0>();
        }
        __syncthreads();

        uint32_t ab = a_base + buf * 16384;
        uint32_t bb = b_base + buf * 16384;
        #pragma unroll
        for (int ks = 0; ks < 4; ks++) {
            int c0 = ks * 2;
            uint32_t af[4][4], bf[4][2];
            #pragma unroll
            for (int mt = 0; mt < 4; mt++) {
                int r = wm * 64 + mt * 16 + (lane & 15);
                int c = c0 + (lane >> 4);
                ldsm4(af[mt], ab + sw(r, c));
            }
            #pragma unroll
            for (int bg = 0; bg < 2; bg++) {
                int r = wn * 32 + bg * 16 + ((lane >> 4) << 3) + (lane & 7);
                int c = c0 + ((lane >> 3) & 1);
                uint32_t q[4];
                ldsm4(q, bb + sw(r, c));
                bf[bg * 2][0] = q[0]; bf[bg * 2][1] = q[1];
                bf[bg * 2 + 1][0] = q[2]; bf[bg * 2 + 1][1] = q[3];
            }
            #pragma unroll
            for (int mt = 0; mt < 4; mt++)
                #pragma unroll
                for (int nt = 0; nt < 4; nt++)
                    mma_f16(acc[mt][nt], af[mt], bf[nt]);
        }
        __syncthreads();
    }

    #pragma unroll
    for (int mt = 0; mt < 4; mt++) {
        #pragma unroll
        for (int h = 0; h < 2; h++) {
            int r = row0 + wm * 64 + mt * 16 + gid + h * 8;
            if (r < N_NODES) {
                #pragma unroll
                for (int nt = 0; nt < 4; nt++) {
                    int c = col0 + wn * 32 + nt * 8 + 2 * tig;
                    float v0 = acc[mt][nt][h * 2 + 0];
                    float v1 = acc[mt][nt][h * 2 + 1];
                    if (RELU) {
                        v0 = fmaxf(v0 + __ldg(&bias[c]), 0.f);
                        v1 = fmaxf(v1 + __ldg(&bias[c + 1]), 0.f);
                    }
                    *(__half2*)(C + (size_t)r * NTOT + c) = __floats2half2_rn(v0, v1);
                }
            }
        }
    }
}

__global__ __launch_bounds__(256) void k_gemm1(const float* __restrict__ b1) {
    gemm_body<128, 256, true>(g_agg, g_w1t, b1, g_h);
}
__global__ __launch_bounds__(256) void k_gemm2(const float* __restrict__ b2) {
    gemm_body<256, 256, true>(g_agg, g_w2t, b2, g_h);
}
__global__ __launch_bounds__(256) void k_gemm3() {
    gemm_body<256, 128, false>(g_h, g_w3t, nullptr, g_xw);
}

// ---------------- fused prep -------------------------------------------------
#define XQ (N_NODES * D_IN / 4)
#define WT1 (D_HID * D_IN)
#define WT2 (D_HID * D_HID)
#define WT3 (D_OUT * D_HID)
#define PREP_TOTAL (N_EDGES + XQ + WT1 + WT2 + WT3)

__global__ void k_prep(const float* __restrict__ ew_raw,
                       const int* __restrict__ dst,
                       const float* __restrict__ x,
                       const float* __restrict__ W1,
                       const float* __restrict__ W2,
                       const float* __restrict__ W3) {
    int i = blockIdx.x * blockDim.x + threadIdx.x;
    if (i < N_EDGES) {
        float w = ew_raw[i];
        float sp = fmaxf(w, 0.0f) + log1pf(expf(-fabsf(w)));
        g_ew[i] = sp;
        int d = dst[i];
        atomicAdd(&g_deg[d], sp);
        atomicAdd(&g_cnt[d], 1);
        return;
    }
    int j = i - N_EDGES;
    if (j < XQ) {
        float4 v = __ldg(&((const float4*)x)[j]);
        uint2 u;
        *(__half2*)&u.x = __floats2half2_rn(v.x, v.y);
        *(__half2*)&u.y = __floats2half2_rn(v.z, v.w);
        ((uint2*)g_xh)[j] = u;
        return;
    }
    j -= XQ;
    if (j < WT1) {
        int n = j / D_IN, k = j % D_IN;
        g_w1t[j] = __float2half_rn(W1[k * D_HID + n]);
        return;
    }
    j -= WT1;
    if (j < WT2) {
        int n = j / D_HID, k = j % D_HID;
        g_w2t[j] = __float2half_rn(W2[k * D_HID + n]);
        return;
    }
    j -= WT2;
    if (j < WT3) {
        int n = j / D_HID, k = j % D_HID;
        g_w3t[j] = __float2half_rn(W3[k * D_OUT + n]);
    }
}

// ---------------- scan -------------------------------------------------------
__global__ void k_scan() {
    __shared__ int s[SCAN_B];
    __shared__ bool isLast;
    int b = blockIdx.x, tid = threadIdx.x;
    int i = b * SCAN_B + tid;
    if (i < N_NODES) g_dinv[i] = rsqrtf(g_deg[i] + 1.0f);
    int v = (i < N_NODES) ? g_cnt[i] : 0;
    s[tid] = v;
    __syncthreads();
    #pragma unroll
    for (int off = 1; off < SCAN_B; off <<= 1) {
        int t = (tid >= off) ? s[tid - off] : 0;
        __syncthreads();
        s[tid] += t;
        __syncthreads();
    }
    int excl = s[tid] - v;
    if (i < N_NODES) { g_rowptr[i] = excl; g_fill[i] = excl; }
    if (i == N_NODES - 1) g_rowptr[N_NODES] = s[tid];
    if (tid == SCAN_B - 1) g_part[b] = s[tid];

    __threadfence();
    __syncthreads();
    if (tid == 0) isLast = (atomicAdd(&g_tick, 1) == NCHUNK - 1);
    __syncthreads();
    if (!isLast) return;
    __threadfence();

    int v2 = (tid < NCHUNK) ? g_part[tid] : 0;
    s[tid] = (tid < 64) ? v2 : 0;
    __syncthreads();
    #pragma unroll
    for (int off = 1; off < 64; off <<= 1) {
        int t = (tid >= off && tid < 64) ? s[tid - off] : 0;
        __syncthreads();
        if (tid < 64) s[tid] += t;
        __syncthreads();
    }
    if (tid < NCHUNK) g_partscan[tid] = s[tid] - v2;
    if (tid == 0) g_tick = 0;
}

// ---------------- place (+deferred reset); weights packed to half2 -----------
__global__ void k_place(const int* __restrict__ src,
                        const int* __restrict__ dst) {
    int i = blockIdx.x * blockDim.x + threadIdx.x;
    if (i < N_EDGES) {
        int s = src[i], d = dst[i];
        float w = g_dinv[s] * g_ew[i] * g_dinv[d];
        unsigned int hw = (unsigned int)__half_as_ushort(__float2half_rn(w));
        int pos = atomicAdd(&g_fill[d], 1) + g_partscan[d >> 10];
        g_csr_src[pos] = s;
        g_csr_wh[pos] = hw | (hw << 16);
    }
    if (i < N_NODES) { g_deg[i] = 0.0f; g_cnt[i] = 0; }
}

// ---------------- aggregation: half2-chain (flush every 4 edges) -------------
template <int DIM, bool OUT_FLOAT>
__device__ __forceinline__ void agg_half_body(const __half* __restrict__ src,
                                              __half* __restrict__ dsth,
                                              float* __restrict__ dstf,
                                              const float* __restrict__ bias) {
    int warp = (blockIdx.x * blockDim.x + threadIdx.x) >> 5;
    int lane = threadIdx.x & 31;
    if (warp >= N_NODES) return;
    constexpr int V = DIM / 128;   // 1: uint2/lane; 2: uint4/lane

    int start = g_rowptr[warp] + g_partscan[warp >> 10];
    int end   = g_rowptr[warp + 1] + g_partscan[(warp + 1) >> 10];
    float di = g_dinv[warp];
    float w0 = di * di;

    // fp32 accumulators: 2*V half2 slots = 4*V floats
    float2 acc[2 * V];
    {
        if (V == 1) {
            uint2 u = __ldg(&((const uint2*)(src + (size_t)warp * DIM))[lane]);
            float2 f0 = __half22float2(u2h2(u.x)), f1 = __half22float2(u2h2(u.y));
            acc[0] = make_float2(w0 * f0.x, w0 * f0.y);
            acc[1] = make_float2(w0 * f1.x, w0 * f1.y);
        } else {
            uint4 u = __ldg(&((const uint4*)(src + (size_t)warp * DIM))[lane]);
            float2 f0 = __half22float2(u2h2(u.x)), f1 = __half22float2(u2h2(u.y));
            float2 f2 = __half22float2(u2h2(u.z)), f3 = __half22float2(u2h2(u.w));
            acc[0] = make_float2(w0 * f0.x, w0 * f0.y);
            acc[1] = make_float2(w0 * f1.x, w0 * f1.y);
            acc[2] = make_float2(w0 * f2.x, w0 * f2.y);
            acc[3] = make_float2(w0 * f3.x, w0 * f3.y);
        }
    }

    int e = start;
    // groups of 4 edges: half2 FMA chains, flush to fp32
    for (; e + 3 < end; e += 4) {
        int s0 = g_csr_src[e],     s1 = g_csr_src[e + 1];
        int s2 = g_csr_src[e + 2], s3 = g_csr_src[e + 3];
        __half2 wh0 = u2h2(g_csr_wh[e]),     wh1 = u2h2(g_csr_wh[e + 1]);
        __half2 wh2 = u2h2(g_csr_wh[e + 2]), wh3 = u2h2(g_csr_wh[e + 3]);
        if (V == 1) {
            uint2 a0 = __ldg(&((const uint2*)(src + (size_t)s0 * DIM))[lane]);
            uint2 a1 = __ldg(&((const uint2*)(src + (size_t)s1 * DIM))[lane]);
            uint2 a2 = __ldg(&((const uint2*)(src + (size_t)s2 * DIM))[lane]);
            uint2 a3 = __ldg(&((const uint2*)(src + (size_t)s3 * DIM))[lane]);
            __half2 h0 = __hmul2(u2h2(a0.x), wh0);
            h0 = __hfma2(u2h2(a1.x), wh1, h0);
            h0 = __hfma2(u2h2(a2.x), wh2, h0);
            h0 = __hfma2(u2h2(a3.x), wh3, h0);
            __half2 h1 = __hmul2(u2h2(a0.y), wh0);
            h1 = __hfma2(u2h2(a1.y), wh1, h1);
            h1 = __hfma2(u2h2(a2.y), wh2, h1);
            h1 = __hfma2(u2h2(a3.y), wh3, h1);
            float2 f0 = __half22float2(h0), f1 = __half22float2(h1);
            acc[0].x += f0.x; acc[0].y += f0.y;
            acc[1].x += f1.x; acc[1].y += f1.y;
        } else {
            uint4 a0 = __ldg(&((const uint4*)(src + (size_t)s0 * DIM))[lane]);
            uint4 a1 = __ldg(&((const uint4*)(src + (size_t)s1 * DIM))[lane]);
            uint4 a2 = __ldg(&((const uint4*)(src + (size_t)s2 * DIM))[lane]);
            uint4 a3 = __ldg(&((const uint4*)(src + (size_t)s3 * DIM))[lane]);
            __half2 h0 = __hmul2(u2h2(a0.x), wh0);
            __half2 h1 = __hmul2(u2h2(a0.y), wh0);
            __half2 h2 = __hmul2(u2h2(a0.z), wh0);
            __half2 h3 = __hmul2(u2h2(a0.w), wh0);
            h0 = __hfma2(u2h2(a1.x), wh1, h0); h1 = __hfma2(u2h2(a1.y), wh1, h1);
            h2 = __hfma2(u2h2(a1.z), wh1, h2); h3 = __hfma2(u2h2(a1.w), wh1, h3);
            h0 = __hfma2(u2h2(a2.x), wh2, h0); h1 = __hfma2(u2h2(a2.y), wh2, h1);
            h2 = __hfma2(u2h2(a2.z), wh2, h2); h3 = __hfma2(u2h2(a2.w), wh2, h3);
            h0 = __hfma2(u2h2(a3.x), wh3, h0); h1 = __hfma2(u2h2(a3.y), wh3, h1);
            h2 = __hfma2(u2h2(a3.z), wh3, h2); h3 = __hfma2(u2h2(a3.w), wh3, h3);
            float2 f0 = __half22float2(h0), f1 = __half22float2(h1);
            float2 f2 = __half22float2(h2), f3 = __half22float2(h3);
            acc[0].x += f0.x; acc[0].y += f0.y;
            acc[1].x += f1.x; acc[1].y += f1.y;
            acc[2].x += f2.x; acc[2].y += f2.y;
            acc[3].x += f3.x; acc[3].y += f3.y;
        }
    }
    // tail (<=3 edges): fp32 path
    for (; e < end; e++) {
        int s0 = g_csr_src[e];
        float w1 = __half2float(__low2half(u2h2(g_csr_wh[e])));
        if (V == 1) {
            uint2 a = __ldg(&((const uint2*)(src + (size_t)s0 * DIM))[lane]);
            float2 f0 = __half22float2(u2h2(a.x)), f1 = __half22float2(u2h2(a.y));
            acc[0].x += w1 * f0.x; acc[0].y += w1 * f0.y;
            acc[1].x += w1 * f1.x; acc[1].y += w1 * f1.y;
        } else {
            uint4 a = __ldg(&((const uint4*)(src + (size_t)s0 * DIM))[lane]);
            float2 f0 = __half22float2(u2h2(a.x)), f1 = __half22float2(u2h2(a.y));
            float2 f2 = __half22float2(u2h2(a.z)), f3 = __half22float2(u2h2(a.w));
            acc[0].x += w1 * f0.x; acc[0].y += w1 * f0.y;
            acc[1].x += w1 * f1.x; acc[1].y += w1 * f1.y;
            acc[2].x += w1 * f2.x; acc[2].y += w1 * f2.y;
            acc[3].x += w1 * f3.x; acc[3].y += w1 * f3.y;
        }
    }

    if (OUT_FLOAT) {   // DIM=128 only
        float4 b4 = __ldg(&((const float4*)bias)[lane]);
        ((float4*)(dstf + (size_t)warp * DIM))[lane] =
            make_float4(acc[0].x + b4.x, acc[0].y + b4.y,
                        acc[1].x + b4.z, acc[1].y + b4.w);
    } else {
        if (V == 1) {
            uint2 u;
            *(__half2*)&u.x = __floats2half2_rn(acc[0].x, acc[0].y);
            *(__half2*)&u.y = __floats2half2_rn(acc[1].x, acc[1].y);
            ((uint2*)(dsth + (size_t)warp * DIM))[lane] = u;
        } else {
            uint4 u;
            *(__half2*)&u.x = __floats2half2_rn(acc[0].x, acc[0].y);
            *(__half2*)&u.y = __floats2half2_rn(acc[1].x, acc[1].y);
            *(__half2*)&u.z = __floats2half2_rn(acc[2].x, acc[2].y);
            *(__half2*)&u.w = __floats2half2_rn(acc[3].x, acc[3].y);
            ((uint4*)(dsth + (size_t)warp * DIM))[lane] = u;
        }
    }
}

__global__ void k_agg_x() {
    agg_half_body<128, false>(g_xh, g_agg, nullptr, nullptr);
}
__global__ void k_agg_h() {
    agg_half_body<256, false>(g_h, g_agg, nullptr, nullptr);
}
__global__ void k_agg_out(float* __restrict__ out, const float* __restrict__ b3) {
    agg_half_body<128, true>(g_xw, nullptr, out, b3);
}

// ---------------- launch -----------------------------------------------------
extern "C" void kernel_launch(void* const* d_in, const int* in_sizes, int n_in,
                              void* d_out, int out_size) {
    const float* x      = (const float*)d_in[0];
    const int*   ei     = (const int*)d_in[1];   // int32 (harness downcasts int64)
    const float* ew_raw = (const float*)d_in[2];
    const float* W1     = (const float*)d_in[3];
    const float* b1     = (const float*)d_in[4];
    const float* W2     = (const float*)d_in[5];
    const float* b2     = (const float*)d_in[6];
    const float* W3     = (const float*)d_in[7];
    const float* b3     = (const float*)d_in[8];
    float* out          = (float*)d_out;

    const int* src = ei;
    const int* dst = ei + N_EDGES;

    const int T = 256;
    int nb_edges = (N_EDGES + T - 1) / T;
    int agg_blocks = (N_NODES * 32 + T - 1) / T;
    int gm = (N_NODES + 127) / 128;   // 391

    const int GEMM_SMEM = 65536;
    cudaFuncSetAttribute(k_gemm1, cudaFuncAttributeMaxDynamicSharedMemorySize, GEMM_SMEM);
    cudaFuncSetAttribute(k_gemm2, cudaFuncAttributeMaxDynamicSharedMemorySize, GEMM_SMEM);
    cudaFuncSetAttribute(k_gemm3, cudaFuncAttributeMaxDynamicSharedMemorySize, GEMM_SMEM);

    k_prep<<<(PREP_TOTAL + T - 1) / T, T>>>(ew_raw, dst, x, W1, W2, W3);
    k_scan<<<NCHUNK, SCAN_B>>>();
    k_place<<<nb_edges, T>>>(src, dst);

    k_agg_x<<<agg_blocks, T>>>();
    k_gemm1<<<dim3(gm, 2), 256, GEMM_SMEM>>>(b1);

    k_agg_h<<<agg_blocks, T>>>();
    k_gemm2<<<dim3(gm, 2), 256, GEMM_SMEM>>>(b2);

    k_gemm3<<<dim3(gm, 1), 256, GEMM_SMEM>>>();
    k_agg_out<<<agg_blocks, T>>>(out, b3);
}

// round 13
// speedup vs baseline: 5.5126x; 1.0601x over previous
#include <cuda_runtime.h>
#include <cuda_fp16.h>
#include <cstdint>

#define N_NODES 50000
#define N_EDGES 600000
#define D_IN 128
#define D_HID 256
#define D_OUT 128
#define SCAN_B 1024
#define NCHUNK ((N_NODES + SCAN_B - 1) / SCAN_B)   // 49

// ---------------- scratch (device globals; bound ONLY in device code) --------
__device__ float g_deg[N_NODES];
__device__ float g_dinv[N_NODES];
__device__ float g_ew[N_EDGES];
__device__ int   g_cnt[N_NODES];
__device__ int   g_rowptr[N_NODES + 1];
__device__ int   g_fill[N_NODES];
__device__ int   g_part[NCHUNK];
__device__ int   g_partscan[NCHUNK];
__device__ int   g_tick;
__device__ int   g_csr_src[N_EDGES];
__device__ unsigned int g_csr_wh[N_EDGES];   // packed half2 {w,w}
__device__ __align__(256) __half g_xh[N_NODES * D_IN];
__device__ __align__(256) __half g_agg[N_NODES * D_HID];
__device__ __align__(256) __half g_h[N_NODES * D_HID];
__device__ __align__(256) __half g_xw[N_NODES * D_OUT];
__device__ __align__(256) __half g_w1t[D_HID * D_IN];
__device__ __align__(256) __half g_w2t[D_HID * D_HID];
__device__ __align__(256) __half g_w3t[D_OUT * D_HID];

// ---------------- asm helpers ------------------------------------------------
__device__ __forceinline__ uint32_t smem_u32(const void* p) {
    uint32_t a;
    asm("{ .reg .u64 t; cvta.to.shared.u64 t, %1; cvt.u32.u64 %0, t; }"
        : "=r"(a) : "l"(p));
    return a;
}
__device__ __forceinline__ void ldsm4(uint32_t* r, uint32_t addr) {
    asm volatile("ldmatrix.sync.aligned.m8n8.x4.shared.b16 {%0,%1,%2,%3}, [%4];"
                 : "=r"(r[0]), "=r"(r[1]), "=r"(r[2]), "=r"(r[3]) : "r"(addr));
}
__device__ __forceinline__ void cpa16(uint32_t saddr, const void* g, bool pred) {
    int sz = pred ? 16 : 0;
    asm volatile("cp.async.ca.shared.global [%0], [%1], 16, %2;"
                 :: "r"(saddr), "l"(g), "r"(sz));
}
__device__ __forceinline__ void cpa_commit() {
    asm volatile("cp.async.commit_group;" ::: "memory");
}
template <int N>
__device__ __forceinline__ void cpa_wait() {
    asm volatile("cp.async.wait_group %0;" :: "n"(N) : "memory");
}
__device__ __forceinline__ void mma_f16(float* c, const uint32_t* a, const uint32_t* b) {
    asm volatile(
        "mma.sync.aligned.m16n8k16.row.col.f32.f16.f16.f32 "
        "{%0,%1,%2,%3}, {%4,%5,%6,%7}, {%8,%9}, {%0,%1,%2,%3};\n"
        : "+f"(c[0]), "+f"(c[1]), "+f"(c[2]), "+f"(c[3])
        : "r"(a[0]), "r"(a[1]), "r"(a[2]), "r"(a[3]), "r"(b[0]), "r"(b[1]));
}
__device__ __forceinline__ uint32_t sw(int r, int c) {
    return (uint32_t)r * 128u + (uint32_t)((c ^ (r & 7)) << 4);
}
__device__ __forceinline__ __half2 u2h2(unsigned int u) {
    __half2 h; *(unsigned int*)&h = u; return h;
}

// ---------------- GEMM body (unchanged; proven) ------------------------------
template <int K, int NTOT, bool RELU>
__device__ __forceinline__ void gemm_body(const __half* __restrict__ A,
                                          const __half* __restrict__ Bt,
                                          const float* __restrict__ bias,
                                          __half* __restrict__ C) {
    extern __shared__ __align__(16) char dsm[];
    uint32_t a_base = smem_u32(dsm);
    uint32_t b_base = a_base + 32768;

    int tid = threadIdx.x;
    int lane = tid & 31, warp = tid >> 5;
    int gid = lane >> 2, tig = lane & 3;
    int wm = warp >> 2, wn = warp & 3;
    int row0 = blockIdx.x * 128;
    int col0 = blockIdx.y * 128;

    float acc[4][4][4];
    #pragma unroll
    for (int mt = 0; mt < 4; mt++)
        #pragma unroll
        for (int nt = 0; nt < 4; nt++)
            #pragma unroll
            for (int q = 0; q < 4; q++) acc[mt][nt][q] = 0.f;

    constexpr int KT = K / 64;

    {
        #pragma unroll
        for (int i = 0; i < 4; i++) {
            int idx = tid + i * 256, r = idx >> 3, c = idx & 7;
            int gr = row0 + r;
            cpa16(a_base + sw(r, c), A + (size_t)gr * K + c * 8, gr < N_NODES);
        }
        #pragma unroll
        for (int i = 0; i < 4; i++) {
            int idx = tid + i * 256, r = idx >> 3, c = idx & 7;
            cpa16(b_base + sw(r, c), Bt + (size_t)(col0 + r) * K + c * 8, true);
        }
        cpa_commit();
    }

    #pragma unroll
    for (int t = 0; t < KT; t++) {
        int buf = t & 1;
        if (t + 1 < KT) {
            int nb_ = (t + 1) & 1, kb = (t + 1) * 64;
            #pragma unroll
            for (int i = 0; i < 4; i++) {
                int idx = tid + i * 256, r = idx >> 3, c = idx & 7;
                int gr = row0 + r;
                cpa16(a_base + nb_ * 16384 + sw(r, c),
                      A + (size_t)gr * K + kb + c * 8, gr < N_NODES);
            }
            #pragma unroll
            for (int i = 0; i < 4; i++) {
                int idx = tid + i * 256, r = idx >> 3, c = idx & 7;
                cpa16(b_base + nb_ * 16384 + sw(r, c),
                      Bt + (size_t)(col0 + r) * K + kb + c * 8, true);
            }
            cpa_commit();
            cpa_wait<1>();
        } else {
            cpa_wait<0>();
        }
        __syncthreads();

        uint32_t ab = a_base + buf * 16384;
        uint32_t bb = b_base + buf * 16384;
        #pragma unroll
        for (int ks = 0; ks < 4; ks++) {
            int c0 = ks * 2;
            uint32_t af[4][4], bf[4][2];
            #pragma unroll
            for (int mt = 0; mt < 4; mt++) {
                int r = wm * 64 + mt * 16 + (lane & 15);
                int c = c0 + (lane >> 4);
                ldsm4(af[mt], ab + sw(r, c));
            }
            #pragma unroll
            for (int bg = 0; bg < 2; bg++) {
                int r = wn * 32 + bg * 16 + ((lane >> 4) << 3) + (lane & 7);
                int c = c0 + ((lane >> 3) & 1);
                uint32_t q[4];
                ldsm4(q, bb + sw(r, c));
                bf[bg * 2][0] = q[0]; bf[bg * 2][1] = q[1];
                bf[bg * 2 + 1][0] = q[2]; bf[bg * 2 + 1][1] = q[3];
            }
            #pragma unroll
            for (int mt = 0; mt < 4; mt++)
                #pragma unroll
                for (int nt = 0; nt < 4; nt++)
                    mma_f16(acc[mt][nt], af[mt], bf[nt]);
        }
        __syncthreads();
    }

    #pragma unroll
    for (int mt = 0; mt < 4; mt++) {
        #pragma unroll
        for (int h = 0; h < 2; h++) {
            int r = row0 + wm * 64 + mt * 16 + gid + h * 8;
            if (r < N_NODES) {
                #pragma unroll
                for (int nt = 0; nt < 4; nt++) {
                    int c = col0 + wn * 32 + nt * 8 + 2 * tig;
                    float v0 = acc[mt][nt][h * 2 + 0];
                    float v1 = acc[mt][nt][h * 2 + 1];
                    if (RELU) {
                        v0 = fmaxf(v0 + __ldg(&bias[c]), 0.f);
                        v1 = fmaxf(v1 + __ldg(&bias[c + 1]), 0.f);
                    }
                    *(__half2*)(C + (size_t)r * NTOT + c) = __floats2half2_rn(v0, v1);
                }
            }
        }
    }
}

__global__ __launch_bounds__(256) void k_gemm1(const float* __restrict__ b1) {
    gemm_body<128, 256, true>(g_agg, g_w1t, b1, g_h);
}
__global__ __launch_bounds__(256) void k_gemm2(const float* __restrict__ b2) {
    gemm_body<256, 256, true>(g_agg, g_w2t, b2, g_h);
}
__global__ __launch_bounds__(256) void k_gemm3() {
    gemm_body<256, 128, false>(g_h, g_w3t, nullptr, g_xw);
}

// ---------------- fused prep -------------------------------------------------
#define XQ (N_NODES * D_IN / 4)
#define WT1 (D_HID * D_IN)
#define WT2 (D_HID * D_HID)
#define WT3 (D_OUT * D_HID)
#define PREP_TOTAL (N_EDGES + XQ + WT1 + WT2 + WT3)

__global__ void k_prep(const float* __restrict__ ew_raw,
                       const int* __restrict__ dst,
                       const float* __restrict__ x,
                       const float* __restrict__ W1,
                       const float* __restrict__ W2,
                       const float* __restrict__ W3) {
    int i = blockIdx.x * blockDim.x + threadIdx.x;
    if (i < N_EDGES) {
        float w = ew_raw[i];
        float sp = fmaxf(w, 0.0f) + log1pf(expf(-fabsf(w)));
        g_ew[i] = sp;
        int d = dst[i];
        atomicAdd(&g_deg[d], sp);
        atomicAdd(&g_cnt[d], 1);
        return;
    }
    int j = i - N_EDGES;
    if (j < XQ) {
        float4 v = __ldg(&((const float4*)x)[j]);
        uint2 u;
        *(__half2*)&u.x = __floats2half2_rn(v.x, v.y);
        *(__half2*)&u.y = __floats2half2_rn(v.z, v.w);
        ((uint2*)g_xh)[j] = u;
        return;
    }
    j -= XQ;
    if (j < WT1) {
        int n = j / D_IN, k = j % D_IN;
        g_w1t[j] = __float2half_rn(W1[k * D_HID + n]);
        return;
    }
    j -= WT1;
    if (j < WT2) {
        int n = j / D_HID, k = j % D_HID;
        g_w2t[j] = __float2half_rn(W2[k * D_HID + n]);
        return;
    }
    j -= WT2;
    if (j < WT3) {
        int n = j / D_HID, k = j % D_HID;
        g_w3t[j] = __float2half_rn(W3[k * D_OUT + n]);
    }
}

// ---------------- scan -------------------------------------------------------
__global__ void k_scan() {
    __shared__ int s[SCAN_B];
    __shared__ bool isLast;
    int b = blockIdx.x, tid = threadIdx.x;
    int i = b * SCAN_B + tid;
    if (i < N_NODES) g_dinv[i] = rsqrtf(g_deg[i] + 1.0f);
    int v = (i < N_NODES) ? g_cnt[i] : 0;
    s[tid] = v;
    __syncthreads();
    #pragma unroll
    for (int off = 1; off < SCAN_B; off <<= 1) {
        int t = (tid >= off) ? s[tid - off] : 0;
        __syncthreads();
        s[tid] += t;
        __syncthreads();
    }
    int excl = s[tid] - v;
    if (i < N_NODES) { g_rowptr[i] = excl; g_fill[i] = excl; }
    if (i == N_NODES - 1) g_rowptr[N_NODES] = s[tid];
    if (tid == SCAN_B - 1) g_part[b] = s[tid];

    __threadfence();
    __syncthreads();
    if (tid == 0) isLast = (atomicAdd(&g_tick, 1) == NCHUNK - 1);
    __syncthreads();
    if (!isLast) return;
    __threadfence();

    int v2 = (tid < NCHUNK) ? g_part[tid] : 0;
    s[tid] = (tid < 64) ? v2 : 0;
    __syncthreads();
    #pragma unroll
    for (int off = 1; off < 64; off <<= 1) {
        int t = (tid >= off && tid < 64) ? s[tid - off] : 0;
        __syncthreads();
        if (tid < 64) s[tid] += t;
        __syncthreads();
    }
    if (tid < NCHUNK) g_partscan[tid] = s[tid] - v2;
    if (tid == 0) g_tick = 0;
}

// ---------------- place (+deferred reset) ------------------------------------
__global__ void k_place(const int* __restrict__ src,
                        const int* __restrict__ dst) {
    int i = blockIdx.x * blockDim.x + threadIdx.x;
    if (i < N_EDGES) {
        int s = src[i], d = dst[i];
        float w = g_dinv[s] * g_ew[i] * g_dinv[d];
        unsigned int hw = (unsigned int)__half_as_ushort(__float2half_rn(w));
        int pos = atomicAdd(&g_fill[d], 1) + g_partscan[d >> 10];
        g_csr_src[pos] = s;
        g_csr_wh[pos] = hw | (hw << 16);
    }
    if (i < N_NODES) { g_deg[i] = 0.0f; g_cnt[i] = 0; }
}

// ---------------- aggregation: 8-edge MLP groups, flush every 4 --------------
template <int DIM, bool OUT_FLOAT>
__device__ __forceinline__ void agg_half_body(const __half* __restrict__ src,
                                              __half* __restrict__ dsth,
                                              float* __restrict__ dstf,
                                              const float* __restrict__ bias) {
    int warp = (blockIdx.x * blockDim.x + threadIdx.x) >> 5;
    int lane = threadIdx.x & 31;
    if (warp >= N_NODES) return;
    constexpr int V = DIM / 128;   // 1: uint2/lane; 2: uint4/lane

    int start = g_rowptr[warp] + g_partscan[warp >> 10];
    int end   = g_rowptr[warp + 1] + g_partscan[(warp + 1) >> 10];
    float di = g_dinv[warp];
    float w0 = di * di;

    float2 acc[2 * V];
    {
        if (V == 1) {
            uint2 u = __ldg(&((const uint2*)(src + (size_t)warp * DIM))[lane]);
            float2 f0 = __half22float2(u2h2(u.x)), f1 = __half22float2(u2h2(u.y));
            acc[0] = make_float2(w0 * f0.x, w0 * f0.y);
            acc[1] = make_float2(w0 * f1.x, w0 * f1.y);
        } else {
            uint4 u = __ldg(&((const uint4*)(src + (size_t)warp * DIM))[lane]);
            float2 f0 = __half22float2(u2h2(u.x)), f1 = __half22float2(u2h2(u.y));
            float2 f2 = __half22float2(u2h2(u.z)), f3 = __half22float2(u2h2(u.w));
            acc[0] = make_float2(w0 * f0.x, w0 * f0.y);
            acc[1] = make_float2(w0 * f1.x, w0 * f1.y);
            acc[2] = make_float2(w0 * f2.x, w0 * f2.y);
            acc[3] = make_float2(w0 * f3.x, w0 * f3.y);
        }
    }

    int e = start;
    // ---- 8-edge groups: all 8 row loads issued up front (MLP=8) ----
    for (; e + 7 < end; e += 8) {
        int sidx[8];
        __half2 wh[8];
        #pragma unroll
        for (int q = 0; q < 8; q++) {
            sidx[q] = g_csr_src[e + q];
            wh[q] = u2h2(g_csr_wh[e + q]);
        }
        if (V == 1) {
            uint2 a[8];
            #pragma unroll
            for (int q = 0; q < 8; q++)
                a[q] = __ldg(&((const uint2*)(src + (size_t)sidx[q] * DIM))[lane]);
            // chain edges 0-3, flush; chain 4-7, flush (same numerics as R12)
            #pragma unroll
            for (int g2 = 0; g2 < 2; g2++) {
                int o = g2 * 4;
                __half2 h0 = __hmul2(u2h2(a[o].x), wh[o]);
                __half2 h1 = __hmul2(u2h2(a[o].y), wh[o]);
                #pragma unroll
                for (int q = 1; q < 4; q++) {
                    h0 = __hfma2(u2h2(a[o + q].x), wh[o + q], h0);
                    h1 = __hfma2(u2h2(a[o + q].y), wh[o + q], h1);
                }
                float2 f0 = __half22float2(h0), f1 = __half22float2(h1);
                acc[0].x += f0.x; acc[0].y += f0.y;
                acc[1].x += f1.x; acc[1].y += f1.y;
            }
        } else {
            uint4 a[8];
            #pragma unroll
            for (int q = 0; q < 8; q++)
                a[q] = __ldg(&((const uint4*)(src + (size_t)sidx[q] * DIM))[lane]);
            #pragma unroll
            for (int g2 = 0; g2 < 2; g2++) {
                int o = g2 * 4;
                __half2 h0 = __hmul2(u2h2(a[o].x), wh[o]);
                __half2 h1 = __hmul2(u2h2(a[o].y), wh[o]);
                __half2 h2 = __hmul2(u2h2(a[o].z), wh[o]);
                __half2 h3 = __hmul2(u2h2(a[o].w), wh[o]);
                #pragma unroll
                for (int q = 1; q < 4; q++) {
                    h0 = __hfma2(u2h2(a[o + q].x), wh[o + q], h0);
                    h1 = __hfma2(u2h2(a[o + q].y), wh[o + q], h1);
                    h2 = __hfma2(u2h2(a[o + q].z), wh[o + q], h2);
                    h3 = __hfma2(u2h2(a[o + q].w), wh[o + q], h3);
                }
                float2 f0 = __half22float2(h0), f1 = __half22float2(h1);
                float2 f2 = __half22float2(h2), f3 = __half22float2(h3);
                acc[0].x += f0.x; acc[0].y += f0.y;
                acc[1].x += f1.x; acc[1].y += f1.y;
                acc[2].x += f2.x; acc[2].y += f2.y;
                acc[3].x += f3.x; acc[3].y += f3.y;
            }
        }
    }
    // ---- 4-edge group ----
    for (; e + 3 < end; e += 4) {
        int sidx[4];
        __half2 wh[4];
        #pragma unroll
        for (int q = 0; q < 4; q++) {
            sidx[q] = g_csr_src[e + q];
            wh[q] = u2h2(g_csr_wh[e + q]);
        }
        if (V == 1) {
            uint2 a[4];
            #pragma unroll
            for (int q = 0; q < 4; q++)
                a[q] = __ldg(&((const uint2*)(src + (size_t)sidx[q] * DIM))[lane]);
            __half2 h0 = __hmul2(u2h2(a[0].x), wh[0]);
            __half2 h1 = __hmul2(u2h2(a[0].y), wh[0]);
            #pragma unroll
            for (int q = 1; q < 4; q++) {
                h0 = __hfma2(u2h2(a[q].x), wh[q], h0);
                h1 = __hfma2(u2h2(a[q].y), wh[q], h1);
            }
            float2 f0 = __half22float2(h0), f1 = __half22float2(h1);
            acc[0].x += f0.x; acc[0].y += f0.y;
            acc[1].x += f1.x; acc[1].y += f1.y;
        } else {
            uint4 a[4];
            #pragma unroll
            for (int q = 0; q < 4; q++)
                a[q] = __ldg(&((const uint4*)(src + (size_t)sidx[q] * DIM))[lane]);
            __half2 h0 = __hmul2(u2h2(a[0].x), wh[0]);
            __half2 h1 = __hmul2(u2h2(a[0].y), wh[0]);
            __half2 h2 = __hmul2(u2h2(a[0].z), wh[0]);
            __half2 h3 = __hmul2(u2h2(a[0].w), wh[0]);
            #pragma unroll
            for (int q = 1; q < 4; q++) {
                h0 = __hfma2(u2h2(a[q].x), wh[q], h0);
                h1 = __hfma2(u2h2(a[q].y), wh[q], h1);
                h2 = __hfma2(u2h2(a[q].z), wh[q], h2);
                h3 = __hfma2(u2h2(a[q].w), wh[q], h3);
            }
            float2 f0 = __half22float2(h0), f1 = __half22float2(h1);
            float2 f2 = __half22float2(h2), f3 = __half22float2(h3);
            acc[0].x += f0.x; acc[0].y += f0.y;
            acc[1].x += f1.x; acc[1].y += f1.y;
            acc[2].x += f2.x; acc[2].y += f2.y;
            acc[3].x += f3.x; acc[3].y += f3.y;
        }
    }
    // ---- scalar tail ----
    for (; e < end; e++) {
        int s0 = g_csr_src[e];
        float w1 = __half2float(__low2half(u2h2(g_csr_wh[e])));
        if (V == 1) {
            uint2 a = __ldg(&((const uint2*)(src + (size_t)s0 * DIM))[lane]);
            float2 f0 = __half22float2(u2h2(a.x)), f1 = __half22float2(u2h2(a.y));
            acc[0].x += w1 * f0.x; acc[0].y += w1 * f0.y;
            acc[1].x += w1 * f1.x; acc[1].y += w1 * f1.y;
        } else {
            uint4 a = __ldg(&((const uint4*)(src + (size_t)s0 * DIM))[lane]);
            float2 f0 = __half22float2(u2h2(a.x)), f1 = __half22float2(u2h2(a.y));
            float2 f2 = __half22float2(u2h2(a.z)), f3 = __half22float2(u2h2(a.w));
            acc[0].x += w1 * f0.x; acc[0].y += w1 * f0.y;
            acc[1].x += w1 * f1.x; acc[1].y += w1 * f1.y;
            acc[2].x += w1 * f2.x; acc[2].y += w1 * f2.y;
            acc[3].x += w1 * f3.x; acc[3].y += w1 * f3.y;
        }
    }

    if (OUT_FLOAT) {   // DIM=128 only
        float4 b4 = __ldg(&((const float4*)bias)[lane]);
        ((float4*)(dstf + (size_t)warp * DIM))[lane] =
            make_float4(acc[0].x + b4.x, acc[0].y + b4.y,
                        acc[1].x + b4.z, acc[1].y + b4.w);
    } else {
        if (V == 1) {
            uint2 u;
            *(__half2*)&u.x = __floats2half2_rn(acc[0].x, acc[0].y);
            *(__half2*)&u.y = __floats2half2_rn(acc[1].x, acc[1].y);
            ((uint2*)(dsth + (size_t)warp * DIM))[lane] = u;
        } else {
            uint4 u;
            *(__half2*)&u.x = __floats2half2_rn(acc[0].x, acc[0].y);
            *(__half2*)&u.y = __floats2half2_rn(acc[1].x, acc[1].y);
            *(__half2*)&u.z = __floats2half2_rn(acc[2].x, acc[2].y);
            *(__half2*)&u.w = __floats2half2_rn(acc[3].x, acc[3].y);
            ((uint4*)(dsth + (size_t)warp * DIM))[lane] = u;
        }
    }
}

__global__ void k_agg_x() {
    agg_half_body<128, false>(g_xh, g_agg, nullptr, nullptr);
}
__global__ void k_agg_h() {
    agg_half_body<256, false>(g_h, g_agg, nullptr, nullptr);
}
__global__ void k_agg_out(float* __restrict__ out, const float* __restrict__ b3) {
    agg_half_body<128, true>(g_xw, nullptr, out, b3);
}

// ---------------- launch -----------------------------------------------------
extern "C" void kernel_launch(void* const* d_in, const int* in_sizes, int n_in,
                              void* d_out, int out_size) {
    const float* x      = (const float*)d_in[0];
    const int*   ei     = (const int*)d_in[1];   // int32 (harness downcasts int64)
    const float* ew_raw = (const float*)d_in[2];
    const float* W1     = (const float*)d_in[3];
    const float* b1     = (const float*)d_in[4];
    const float* W2     = (const float*)d_in[5];
    const float* b2     = (const float*)d_in[6];
    const float* W3     = (const float*)d_in[7];
    const float* b3     = (const float*)d_in[8];
    float* out          = (float*)d_out;

    const int* src = ei;
    const int* dst = ei + N_EDGES;

    const int T = 256;
    int nb_edges = (N_EDGES + T - 1) / T;
    int agg_blocks = (N_NODES * 32 + T - 1) / T;
    int gm = (N_NODES + 127) / 128;   // 391

    const int GEMM_SMEM = 65536;
    cudaFuncSetAttribute(k_gemm1, cudaFuncAttributeMaxDynamicSharedMemorySize, GEMM_SMEM);
    cudaFuncSetAttribute(k_gemm2, cudaFuncAttributeMaxDynamicSharedMemorySize, GEMM_SMEM);
    cudaFuncSetAttribute(k_gemm3, cudaFuncAttributeMaxDynamicSharedMemorySize, GEMM_SMEM);

    k_prep<<<(PREP_TOTAL + T - 1) / T, T>>>(ew_raw, dst, x, W1, W2, W3);
    k_scan<<<NCHUNK, SCAN_B>>>();
    k_place<<<nb_edges, T>>>(src, dst);

    k_agg_x<<<agg_blocks, T>>>();
    k_gemm1<<<dim3(gm, 2), 256, GEMM_SMEM>>>(b1);

    k_agg_h<<<agg_blocks, T>>>();
    k_gemm2<<<dim3(gm, 2), 256, GEMM_SMEM>>>(b2);

    k_gemm3<<<dim3(gm, 1), 256, GEMM_SMEM>>>();
    k_agg_out<<<agg_blocks, T>>>(out, b3);
}